// round 9
// baseline (speedup 1.0000x reference)
#include <cuda_runtime.h>
#include <math.h>
#include <float.h>

// ---------------- problem constants ----------------
#define NB_    8
#define TT_    497
#define LAUD_  32000
#define HOP_   64
#define NFFT_  256
#define AE_    256
#define BTL_   256
#define HH_    512
#define FC_    385
#define FCP_   400        // padded stride for xc (K=385 -> 25*16)
#define NFREQ_ 129
#define EMBD_  20
#define NBLK_  32
#define NPAIR_ 15
#define KPACK_ 514
#define KPACKP_ 528       // padded stride for rows (33*16)
#define GNS_   32
#define ANS_   64
#define MROWS_ (NB_*TT_)          // 3976
#define MROWS2_ (NB_*2*TT_)       // 7952
#define NSEP_  (FC_*EMBD_)        // 7700

// ---------------- device scratch ----------------
__device__ float g_frames[MROWS_*NFFT_];
__device__ float g_enc[MROWS_*AE_];
__device__ float g_Re[MROWS_*NFREQ_];
__device__ float g_Im[MROWS_*NFREQ_];
__device__ float g_mag[MROWS_*NFREQ_];
__device__ float g_xc[MROWS_*FCP_];
__device__ float g_x[MROWS_*BTL_];
__device__ float g_y1[MROWS_*HH_];
__device__ float g_y2[MROWS_*HH_];
__device__ float g_emb[(long)MROWS_*NSEP_];
__device__ float g_rows[(long)MROWS2_*KPACKP_];
__device__ float g_tot[MROWS2_*NFFT_];
__device__ double g_part[NB_*GNS_*2];
__device__ float g_apart[NB_*NPAIR_*ANS_*42];
__device__ float g_attrAll[NB_*NPAIR_*40];
__device__ float g_sp01[NB_*NPAIR_];
__device__ float g_att[NB_*40];
__device__ float g_c256[256], g_s256[256], g_win[256], g_invwin[256];
__device__ float g_Bpack[KPACK_*256], g_biasPack[256];
__device__ float g_Wg[NBLK_*HH_*BTL_];
__device__ float g_u[NBLK_*BTL_], g_v[NBLK_*BTL_];

__constant__ int d_combs[NPAIR_][2] = {
  {0,1},{0,2},{0,3},{0,4},{0,5},{1,2},{1,3},{1,4},{1,5},
  {2,3},{2,4},{2,5},{3,4},{3,5},{4,5}
};

// ---------------- tf32 helpers ----------------
__device__ __forceinline__ void split_tf32(float x, float& h, float& l) {
  unsigned hu;
  asm("cvt.rna.tf32.f32 %0, %1;" : "=r"(hu) : "f"(x));
  h = __uint_as_float(hu);
  float r = x - h;
  unsigned lu;
  asm("cvt.rna.tf32.f32 %0, %1;" : "=r"(lu) : "f"(r));
  l = __uint_as_float(lu);
}
__device__ __forceinline__ void split4(const float4& v, float4& h, float4& l) {
  split_tf32(v.x, h.x, l.x);
  split_tf32(v.y, h.y, l.y);
  split_tf32(v.z, h.z, l.z);
  split_tf32(v.w, h.w, l.w);
}
__device__ __forceinline__ void mma8(float* c, const unsigned* a, const unsigned* b) {
  asm volatile(
    "mma.sync.aligned.m16n8k8.row.col.f32.tf32.tf32.f32 "
    "{%0,%1,%2,%3}, {%4,%5,%6,%7}, {%8,%9}, {%0,%1,%2,%3};\n"
    : "+f"(c[0]), "+f"(c[1]), "+f"(c[2]), "+f"(c[3])
    : "r"(a[0]), "r"(a[1]), "r"(a[2]), "r"(a[3]), "r"(b[0]), "r"(b[1]));
}

// ---------------- tables / weight prep ----------------
__global__ void init_tables_k(float* c, float* s, float* win, float* invwin) {
  int n = threadIdx.x;
  double a = 2.0 * 3.14159265358979323846 * (double)n / 256.0;
  double cv = cos(a), sv = sin(a);
  c[n] = (float)cv; s[n] = (float)sv;
  float w = (float)sqrt(0.5 - 0.5 * cv);
  win[n] = w;
  __syncthreads();
  __shared__ float dn[64];
  if (n < 64) {
    float d = 0.f;
    for (int q = 0; q < 4; q++) { float wv = win[n + 64*q]; d += wv*wv; }
    dn[n] = d;
  }
  __syncthreads();
  invwin[n] = win[n] / dn[n & 63];
}

__global__ void pack_k(const float* __restrict__ dec_w, const float* __restrict__ dec_b,
                       const float* __restrict__ c, const float* __restrict__ s,
                       const float* __restrict__ invwin,
                       float* __restrict__ Bp, float* __restrict__ biasP) {
  int k = blockIdx.x, n = threadIdx.x;
  float v;
  if (k < 256) {
    v = 0.5f * dec_w[k*256 + n];
  } else if (k < 385) {
    int j = k - 256;
    float wj = (j == 0 || j == 128) ? 1.f : 2.f;
    int m = (j * n) & 255;
    v = 0.5f * invwin[n] * wj * c[m] * (1.f/256.f);
  } else {
    int j = k - 385;
    float wj = (j == 0 || j == 128) ? 1.f : 2.f;
    int m = (j * n) & 255;
    v = -0.5f * invwin[n] * wj * s[m] * (1.f/256.f);
  }
  Bp[k*256 + n] = v;
  if (k == 0) biasP[n] = 0.5f * dec_b[n];
}

__global__ void prep_c2_k(const float* __restrict__ c2w, const float* __restrict__ g2g,
                          const float* __restrict__ g2b,
                          float* __restrict__ Wg, float* __restrict__ u, float* __restrict__ v) {
  int i = blockIdx.x;
  int n = blockIdx.y * 128 + threadIdx.x;
  const float* W  = c2w + (long)i*HH_*BTL_;
  const float* gg = g2g + i*HH_;
  const float* bb = g2b + i*HH_;
  float* Wo = Wg + (long)i*HH_*BTL_;
  float au = 0.f, av = 0.f;
  for (int k = 0; k < HH_; k++) {
    float w = W[k*BTL_ + n];
    float wg = gg[k] * w;
    au = fmaf(bb[k], w, au);
    av += wg;
    Wo[k*BTL_ + n] = wg;
  }
  u[i*BTL_ + n] = au;
  v[i*BTL_ + n] = av;
}

// ---------------- framing ----------------
__global__ void frames_k(const float* __restrict__ aud, float* __restrict__ frames) {
  int bt = blockIdx.x, n = threadIdx.x;
  int b = bt / TT_, t = bt % TT_;
  int off = b * 2 * LAUD_ + t * HOP_ + n;
  frames[bt * NFFT_ + n] = aud[off] + aud[off + LAUD_];
}

// ---------------- rDFT ----------------
__global__ void fft_k(const float* __restrict__ frames, const float* __restrict__ win,
                      const float* __restrict__ c, const float* __restrict__ s,
                      float* __restrict__ Re, float* __restrict__ Im, float* __restrict__ Mag) {
  int bt = blockIdx.x, tid = threadIdx.x;
  __shared__ float row[256], sc[256], ss[256];
  row[tid] = frames[bt*NFFT_ + tid] * win[tid];
  sc[tid] = c[tid]; ss[tid] = s[tid];
  __syncthreads();
  if (tid < NFREQ_) {
    int j = tid;
    float re = 0.f, im = 0.f;
    int m = 0;
    #pragma unroll 8
    for (int n = 0; n < 256; n++) {
      float v = row[n];
      re = fmaf(v, sc[m], re);
      im = fmaf(-v, ss[m], im);
      m = (m + j) & 255;
    }
    Re[bt*NFREQ_ + j] = re;
    Im[bt*NFREQ_ + j] = im;
    Mag[bt*NFREQ_ + j] = sqrtf(re*re + im*im);
  }
}

// ---------------- cLN ----------------
__global__ void cln_k(const float* __restrict__ enc, const float* __restrict__ mag,
                      const float* __restrict__ gamma, const float* __restrict__ beta,
                      float* __restrict__ xc) {
  int bt = blockIdx.x, tid = threadIdx.x;
  __shared__ float vals[FC_];
  for (int f = tid; f < FC_; f += 128)
    vals[f] = (f < AE_) ? enc[bt*AE_ + f] : log1pf(mag[bt*NFREQ_ + (f - AE_)]);
  __syncthreads();
  double s = 0.0, ss = 0.0;
  for (int f = tid; f < FC_; f += 128) { double v = vals[f]; s += v; ss += v*v; }
  __shared__ double rs[128], rss[128];
  rs[tid] = s; rss[tid] = ss; __syncthreads();
  for (int o = 64; o > 0; o >>= 1) {
    if (tid < o) { rs[tid] += rs[tid+o]; rss[tid] += rss[tid+o]; }
    __syncthreads();
  }
  __shared__ float mS, iS;
  if (tid == 0) {
    double m = rs[0] / FC_;
    double var = rss[0] / FC_ - m*m;
    mS = (float)m; iS = (float)rsqrt(var + 1e-12);
  }
  __syncthreads();
  for (int f = tid; f < FC_; f += 128)
    xc[bt*FCP_ + f] = (vals[f] - mS) * iS * gamma[f] + beta[f];
  for (int f = FC_ + tid; f < FCP_; f += 128)
    xc[bt*FCP_ + f] = 0.f;
}

// ---------------- tf32 tensor-core GEMM v4 ----------------
// Block 64x64x16, 256 threads = 8 warps (2M x 4N), warp tile 32x16.
// Raw fp32 loaded from global (1x traffic); split to tf32 (hi,lo) ONCE per
// element at smem-store time into Ah/Al/Bh/Bl (XOR-swizzled, conflict-free).
// Inner loop: pure LDS + MMA, 3xTF32 compensation.
// PTX m16n8k8.tf32 fragments (g=lane>>2, t=lane&3):
//   A: a0=A[g][t] a1=A[g+8][t] a2=A[g][t+4] a3=A[g+8][t+4]
//   B: b0=B[t][n] b1=B[t+4][n]
//   C: c0=[g][2t] c1=[g][2t+1] c2=[g+8][2t] c3=[g+8][2t+1]
// Requires lda >= ceil(K/16)*16 with zero padding in A rows beyond K.
// EPI: 0 none, 1 relu, 2 prelu(col), 3 residual-add + per-batch gLN affine
template<int EPI>
__global__ __launch_bounds__(256, 2)
void gemmT(const float* __restrict__ A, const float* __restrict__ Bm,
           const float* __restrict__ bias, float* __restrict__ C,
           int M, int N, int K, int lda,
           const float* __restrict__ prelu,
           const float* __restrict__ uvec, const float* __restrict__ vvec,
           const double* __restrict__ part) {
  constexpr int BM = 64, BN = 64, BK = 16;
  __shared__ float Ah[2][BM][BK], Al[2][BM][BK];   // col k ^ (4*((m>>1)&3))
  __shared__ float Bh[2][BK][BN], Bl[2][BK][BN];   // col n ^ (8*(k&3))
  __shared__ float s_m[8], s_i[8];

  const int tid = threadIdx.x;
  if (EPI == 3 && tid < 8) {
    double sm = 0.0, ss = 0.0;
    for (int q = 0; q < GNS_; q++) {
      sm += part[(tid*GNS_+q)*2];
      ss += part[(tid*GNS_+q)*2 + 1];
    }
    const double pb = (double)(TT_*HH_);
    double mm = sm / pb;
    s_m[tid] = (float)mm;
    s_i[tid] = (float)rsqrt(ss / pb - mm*mm + 1e-12);
  }

  const int row0 = blockIdx.y * BM, col0 = blockIdx.x * BN;
  const int wid = tid >> 5, lane = tid & 31;
  const int g = lane >> 2, t = lane & 3;
  const int m0w = (wid >> 2) * 32;      // 0 or 32
  const int n0w = (wid & 3) * 16;       // 0,16,32,48

  float acc[2][2][4];
  #pragma unroll
  for (int i = 0; i < 2; i++)
    #pragma unroll
    for (int j = 0; j < 2; j++)
      #pragma unroll
      for (int q = 0; q < 4; q++) acc[i][j][q] = 0.f;

  float4 aR, bR;
  const int am = tid >> 2, ak4 = (tid & 3) << 2;
  const int asw = ak4 ^ (4 * ((am >> 1) & 3));
  const int bk = tid >> 4, bn4 = (tid & 15) << 2;
  const int bswst = bn4 ^ (8 * (bk & 3));

  auto loadA = [&](int kt) {
    int row = row0 + am;
    float4 r = make_float4(0.f, 0.f, 0.f, 0.f);
    if (row < M) r = *(const float4*)(A + (long)row * lda + kt * BK + ak4);
    aR = r;
  };
  auto loadB = [&](int kt) {
    int gk = kt * BK + bk, col = col0 + bn4;
    float4 r = make_float4(0.f, 0.f, 0.f, 0.f);
    if (gk < K) {
      const float* bp = Bm + (long)gk * N + col;
      if (col + 3 < N) r = *(const float4*)bp;
      else {
        if (col     < N) r.x = bp[0];
        if (col + 1 < N) r.y = bp[1];
        if (col + 2 < N) r.z = bp[2];
      }
    }
    bR = r;
  };
  auto storeT = [&](int buf) {
    float4 h4, l4;
    split4(aR, h4, l4);
    *(float4*)&Ah[buf][am][asw] = h4;
    *(float4*)&Al[buf][am][asw] = l4;
    split4(bR, h4, l4);
    *(float4*)&Bh[buf][bk][bswst] = h4;
    *(float4*)&Bl[buf][bk][bswst] = l4;
  };

  const int ktot = (K + BK - 1) / BK;
  loadA(0); loadB(0);
  storeT(0);
  __syncthreads();

  for (int kt = 0; kt < ktot; kt++) {
    const int buf = kt & 1;
    const bool more = (kt + 1 < ktot);
    if (more) { loadA(kt + 1); loadB(kt + 1); }

    #pragma unroll
    for (int ks = 0; ks < 2; ks++) {
      const int k1 = ks * 8 + t, k2 = k1 + 4;
      unsigned ah[2][4], al[2][4];
      #pragma unroll
      for (int mi = 0; mi < 2; mi++) {
        int rA = m0w + mi * 16 + g;
        int sw = 4 * ((rA >> 1) & 3);       // same for rA and rA+8
        ah[mi][0] = __float_as_uint(Ah[buf][rA    ][k1 ^ sw]);
        ah[mi][1] = __float_as_uint(Ah[buf][rA + 8][k1 ^ sw]);
        ah[mi][2] = __float_as_uint(Ah[buf][rA    ][k2 ^ sw]);
        ah[mi][3] = __float_as_uint(Ah[buf][rA + 8][k2 ^ sw]);
        al[mi][0] = __float_as_uint(Al[buf][rA    ][k1 ^ sw]);
        al[mi][1] = __float_as_uint(Al[buf][rA + 8][k1 ^ sw]);
        al[mi][2] = __float_as_uint(Al[buf][rA    ][k2 ^ sw]);
        al[mi][3] = __float_as_uint(Al[buf][rA + 8][k2 ^ sw]);
      }
      unsigned bh[2][2], bl[2][2];
      const int bsw = 8 * (k1 & 3);         // k1&3 == k2&3
      #pragma unroll
      for (int ni = 0; ni < 2; ni++) {
        int cn = (n0w + ni * 8 + g) ^ bsw;
        bh[ni][0] = __float_as_uint(Bh[buf][k1][cn]);
        bh[ni][1] = __float_as_uint(Bh[buf][k2][cn]);
        bl[ni][0] = __float_as_uint(Bl[buf][k1][cn]);
        bl[ni][1] = __float_as_uint(Bl[buf][k2][cn]);
      }
      #pragma unroll
      for (int mi = 0; mi < 2; mi++)
        #pragma unroll
        for (int ni = 0; ni < 2; ni++) {
          mma8(acc[mi][ni], ah[mi], bl[ni]);
          mma8(acc[mi][ni], al[mi], bh[ni]);
          mma8(acc[mi][ni], ah[mi], bh[ni]);
        }
    }

    if (more) { storeT(buf ^ 1); __syncthreads(); }
  }

  // epilogue: c-fragment row = g + ii*8, col = 2t + jj
  #pragma unroll
  for (int mi = 0; mi < 2; mi++) {
    #pragma unroll
    for (int ii = 0; ii < 2; ii++) {
      int row = row0 + m0w + mi * 16 + g + ii * 8;
      if (row >= M) continue;
      float si = 1.f, smn = 0.f;
      if (EPI == 3) { int b = row / TT_; si = s_i[b]; smn = s_m[b]; }
      float* crow = C + (long)row * N;
      #pragma unroll
      for (int ni = 0; ni < 2; ni++) {
        #pragma unroll
        for (int jj = 0; jj < 2; jj++) {
          int cc = col0 + n0w + ni * 8 + 2 * t + jj;
          if (cc >= N) continue;
          float vx = acc[mi][ni][ii * 2 + jj];
          if (EPI == 0) vx += bias[cc];
          if (EPI == 1) { vx += bias[cc]; vx = fmaxf(vx, 0.f); }
          if (EPI == 2) { vx += bias[cc]; vx = fmaxf(vx, 0.f) + prelu[cc] * fminf(vx, 0.f); }
          if (EPI == 3) vx = crow[cc] + si * vx + (uvec[cc] - smn * si * vvec[cc]) + bias[cc];
          crow[cc] = vx;
        }
      }
    }
  }
}

// ---------------- gLN partial stats ----------------
__global__ void stat1_k(const float* __restrict__ x, double* __restrict__ part) {
  int b = blockIdx.x >> 5, s = blockIdx.x & 31;
  const int tot4 = TT_*HH_/4;
  const int chunk4 = tot4 / GNS_;
  int st = s * chunk4, en = st + chunk4;
  const float4* x4 = (const float4*)(x + (long)b * TT_ * HH_);
  double sm = 0.0, ss = 0.0;
  for (int i = st + threadIdx.x; i < en; i += 256) {
    float4 v = x4[i];
    sm += (double)v.x + v.y + v.z + v.w;
    ss += (double)v.x*v.x + (double)v.y*v.y + (double)v.z*v.z + (double)v.w*v.w;
  }
  __shared__ double rs[256], rss[256];
  int tid = threadIdx.x;
  rs[tid] = sm; rss[tid] = ss; __syncthreads();
  for (int o = 128; o > 0; o >>= 1) {
    if (tid < o) { rs[tid] += rs[tid+o]; rss[tid] += rss[tid+o]; }
    __syncthreads();
  }
  if (tid == 0) { part[(b*GNS_+s)*2] = rs[0]; part[(b*GNS_+s)*2+1] = rss[0]; }
}

// ---------------- dwconv ----------------
__global__ __launch_bounds__(256)
void dwconv2_k(const float* __restrict__ y1, float* __restrict__ y2,
               const float* __restrict__ w, const double* __restrict__ part,
               const float* __restrict__ g, const float* __restrict__ be,
               const float* __restrict__ p2, int d) {
  __shared__ float s_m[8], s_i[8];
  int tid = threadIdx.x;
  if (tid < 8) {
    double sm = 0.0, ss = 0.0;
    for (int q = 0; q < GNS_; q++) {
      sm += part[(tid*GNS_+q)*2];
      ss += part[(tid*GNS_+q)*2 + 1];
    }
    const double pb = (double)(TT_*HH_);
    double mm = sm / pb;
    s_m[tid] = (float)mm;
    s_i[tid] = (float)rsqrt(ss / pb - mm*mm + 1e-12);
  }
  __syncthreads();
  int idx4 = blockIdx.x * 256 + tid;
  if (idx4 >= MROWS_ * HH_ / 4) return;
  int c4 = (idx4 & 127) << 2;
  int bt = idx4 >> 7;
  int t = bt % TT_, b = bt / TT_;
  float m = s_m[b], si = s_i[b];
  float4 gg = *(const float4*)(g + c4);
  float4 bb = *(const float4*)(be + c4);
  float4 pp = *(const float4*)(p2 + c4);
  float4 acc = make_float4(0.f,0.f,0.f,0.f);
  #pragma unroll
  for (int k = 0; k < 3; k++) {
    int tt = t + (k - 1) * d;
    if (tt >= 0 && tt < TT_) {
      float4 v = *(const float4*)(y1 + ((long)(b*TT_ + tt))*HH_ + c4);
      float4 wv = *(const float4*)(w + k*HH_ + c4);
      acc.x = fmaf(wv.x, (v.x - m)*si*gg.x + bb.x, acc.x);
      acc.y = fmaf(wv.y, (v.y - m)*si*gg.y + bb.y, acc.y);
      acc.z = fmaf(wv.z, (v.z - m)*si*gg.z + bb.z, acc.z);
      acc.w = fmaf(wv.w, (v.w - m)*si*gg.w + bb.w, acc.w);
    }
  }
  float4 o;
  o.x = fmaxf(acc.x, 0.f) + pp.x * fminf(acc.x, 0.f);
  o.y = fmaxf(acc.y, 0.f) + pp.y * fminf(acc.y, 0.f);
  o.z = fmaxf(acc.z, 0.f) + pp.z * fminf(acc.z, 0.f);
  o.w = fmaxf(acc.w, 0.f) + pp.w * fminf(acc.w, 0.f);
  *(float4*)(y2 + (long)idx4*4) = o;
}

// ---------------- attractor ----------------
__device__ __forceinline__ float warp_sum(float x) {
  #pragma unroll
  for (int o = 16; o > 0; o >>= 1) x += __shfl_down_sync(0xffffffffu, x, o);
  return x;
}

__global__ __launch_bounds__(128)
void attr_part_k(const float* __restrict__ emb, const float* __restrict__ anchors,
                 float* __restrict__ part) {
  int bp = blockIdx.x % (NB_*NPAIR_);
  int s  = blockIdx.x / (NB_*NPAIR_);
  int b = bp / NPAIR_, p = bp % NPAIR_;
  int tid = threadIdx.x;
  __shared__ float a0[EMBD_], a1[EMBD_];
  if (tid < EMBD_) {
    a0[tid] = anchors[d_combs[p][0] * EMBD_ + tid];
    a1[tid] = anchors[d_combs[p][1] * EMBD_ + tid];
  }
  __syncthreads();
  const int rows = TT_ * FC_;
  int chunk = (rows + ANS_ - 1) / ANS_;
  int st = s * chunk, en = min(rows, st + chunk);
  float num0[EMBD_], sev[EMBD_];
  #pragma unroll
  for (int i = 0; i < EMBD_; i++) { num0[i] = 0.f; sev[i] = 0.f; }
  float den0 = 0.f;
  const float* base = emb + (long)b * rows * EMBD_;
  for (int r = st + tid; r < en; r += 128) {
    const float4* e4 = (const float4*)(base + (long)r * EMBD_);
    float ev[EMBD_];
    #pragma unroll
    for (int q = 0; q < 5; q++) {
      float4 v = e4[q];
      ev[q*4+0] = v.x; ev[q*4+1] = v.y; ev[q*4+2] = v.z; ev[q*4+3] = v.w;
    }
    float dd0 = 0.f, dd1 = 0.f;
    #pragma unroll
    for (int i = 0; i < EMBD_; i++) { dd0 = fmaf(ev[i], a0[i], dd0); dd1 = fmaf(ev[i], a1[i], dd1); }
    float s0 = 1.f / (1.f + expf(dd1 - dd0));
    den0 += s0;
    #pragma unroll
    for (int i = 0; i < EMBD_; i++) { num0[i] = fmaf(s0, ev[i], num0[i]); sev[i] += ev[i]; }
  }
  __shared__ float red[4][41];
  int lane = tid & 31, w = tid >> 5;
  den0 = warp_sum(den0);
  #pragma unroll
  for (int i = 0; i < EMBD_; i++) { num0[i] = warp_sum(num0[i]); sev[i] = warp_sum(sev[i]); }
  if (lane == 0) {
    red[w][0] = den0;
    #pragma unroll
    for (int i = 0; i < EMBD_; i++) { red[w][1+i] = num0[i]; red[w][21+i] = sev[i]; }
  }
  __syncthreads();
  if (tid < 41) {
    float a = red[0][tid] + red[1][tid] + red[2][tid] + red[3][tid];
    part[(bp * ANS_ + s) * 42 + tid] = a;
  }
}

__global__ void attr_comb_k(const float* __restrict__ part, float* __restrict__ attrAll,
                            float* __restrict__ sp01) {
  int bp = blockIdx.x, tid = threadIdx.x;
  __shared__ float comb[41];
  if (tid < 41) {
    double a = 0.0;
    for (int s = 0; s < ANS_; s++) a += part[(bp * ANS_ + s) * 42 + tid];
    comb[tid] = (float)a;
  }
  __syncthreads();
  __shared__ float at[40];
  if (tid < 40) {
    int c = tid / EMBD_, e = tid % EMBD_;
    float den0 = comb[0];
    float den1 = (float)(TT_ * FC_) - den0;
    float val;
    if (c == 0) val = comb[1 + e] / den0;
    else        val = (comb[21 + e] - comb[1 + e]) / den1;
    at[tid] = val;
    attrAll[bp * 40 + tid] = val;
  }
  __syncthreads();
  if (tid == 0) {
    float s = 0.f;
    for (int e = 0; e < EMBD_; e++) s += at[e] * at[EMBD_ + e];
    sp01[bp] = s;
  }
}

__global__ void choose_k(const float* __restrict__ sp01, const float* __restrict__ attrAll,
                         float* __restrict__ attract) {
  int b = threadIdx.x;
  if (b >= NB_) return;
  float best = sp01[b * NPAIR_];
  int bi = 0;
  for (int p = 1; p < NPAIR_; p++) {
    float v = sp01[b * NPAIR_ + p];
    if (v < best) { best = v; bi = p; }
  }
  for (int k = 0; k < 40; k++)
    attract[b * 40 + k] = attrAll[(b * NPAIR_ + bi) * 40 + k];
}

// ---------------- code rows ----------------
__global__ __launch_bounds__(128)
void code_k(const float* __restrict__ emb, const float* __restrict__ attract,
            const float* __restrict__ enc, const float* __restrict__ Re,
            const float* __restrict__ Im, float* __restrict__ rows) {
  int bt = blockIdx.x, tid = threadIdx.x;
  int b = bt / TT_, t = bt % TT_;
  __shared__ float at[40];
  if (tid < 40) at[tid] = attract[b * 40 + tid];
  __syncthreads();
  long r0 = ((long)(b * 2 + 0) * TT_ + t) * KPACKP_;
  long r1 = ((long)(b * 2 + 1) * TT_ + t) * KPACKP_;
  for (int f = tid; f < FC_; f += 128) {
    const float4* e4 = (const float4*)(emb + ((long)bt * FC_ + f) * EMBD_);
    float l0 = 0.f, l1 = 0.f;
    #pragma unroll
    for (int q = 0; q < 5; q++) {
      float4 v = e4[q];
      l0 = fmaf(v.x, at[q*4+0], l0); l0 = fmaf(v.y, at[q*4+1], l0);
      l0 = fmaf(v.z, at[q*4+2], l0); l0 = fmaf(v.w, at[q*4+3], l0);
      l1 = fmaf(v.x, at[20+q*4+0], l1); l1 = fmaf(v.y, at[20+q*4+1], l1);
      l1 = fmaf(v.z, at[20+q*4+2], l1); l1 = fmaf(v.w, at[20+q*4+3], l1);
    }
    if (f < AE_) {
      float fe = enc[bt * AE_ + f];
      rows[r0 + f] = l0 * fe;
      rows[r1 + f] = l1 * fe;
    } else {
      int j = f - AE_;
      float re = Re[bt * NFREQ_ + j], im = Im[bt * NFREQ_ + j];
      rows[r0 + 256 + j] = l0 * re;
      rows[r0 + 385 + j] = l0 * im;
      rows[r1 + 256 + j] = l1 * re;
      rows[r1 + 385 + j] = l1 * im;
    }
  }
  if (tid < KPACKP_ - KPACK_) {
    rows[r0 + KPACK_ + tid] = 0.f;
    rows[r1 + KPACK_ + tid] = 0.f;
  }
}

// ---------------- overlap-add ----------------
__global__ void ola_k(const float* __restrict__ tot, float* __restrict__ out) {
  int idx = blockIdx.x * blockDim.x + threadIdx.x;
  if (idx >= NB_ * 2 * LAUD_) return;
  int l = idx % LAUD_;
  int bc = idx / LAUD_;
  int tlo = (l >= NFFT_) ? ((l - NFFT_) >> 6) + 1 : 0;
  int thi = min(TT_ - 1, l >> 6);
  float acc = 0.f;
  for (int t = tlo; t <= thi; t++)
    acc += tot[((long)bc * TT_ + t) * NFFT_ + (l - (t << 6))];
  out[idx] = acc;
}

// ---------------- host orchestration ----------------
extern "C" void kernel_launch(void* const* d_in, const int* in_sizes, int n_in,
                              void* d_out, int out_size) {
  const float* audios = (const float*)d_in[0];
  const float* enc_w  = (const float*)d_in[1];
  const float* enc_b  = (const float*)d_in[2];
  const float* bgam   = (const float*)d_in[3];
  const float* bbet   = (const float*)d_in[4];
  const float* bw     = (const float*)d_in[5];
  const float* bbi    = (const float*)d_in[6];
  const float* c1w    = (const float*)d_in[7];
  const float* c1b    = (const float*)d_in[8];
  const float* p1     = (const float*)d_in[9];
  const float* g1g    = (const float*)d_in[10];
  const float* g1b    = (const float*)d_in[11];
  const float* dwv    = (const float*)d_in[12];
  const float* p2     = (const float*)d_in[13];
  const float* g2g    = (const float*)d_in[14];
  const float* g2b    = (const float*)d_in[15];
  const float* c2w    = (const float*)d_in[16];
  const float* c2b    = (const float*)d_in[17];
  const float* sw     = (const float*)d_in[18];
  const float* sb     = (const float*)d_in[19];
  const float* anchors= (const float*)d_in[20];
  const float* dec_w  = (const float*)d_in[21];
  const float* dec_b  = (const float*)d_in[22];
  float* out = (float*)d_out;

  float *frames,*enc,*Re,*Im,*mag,*xc,*x,*y1,*y2,*emb,*rows,*tot;
  float *apart,*attrAll,*sp01,*attv;
  float *c256,*s256,*win,*invwin,*Bpack,*biasPack,*Wg,*uv,*vv;
  double *part;
  cudaGetSymbolAddress((void**)&frames, g_frames);
  cudaGetSymbolAddress((void**)&enc,    g_enc);
  cudaGetSymbolAddress((void**)&Re,     g_Re);
  cudaGetSymbolAddress((void**)&Im,     g_Im);
  cudaGetSymbolAddress((void**)&mag,    g_mag);
  cudaGetSymbolAddress((void**)&xc,     g_xc);
  cudaGetSymbolAddress((void**)&x,      g_x);
  cudaGetSymbolAddress((void**)&y1,     g_y1);
  cudaGetSymbolAddress((void**)&y2,     g_y2);
  cudaGetSymbolAddress((void**)&emb,    g_emb);
  cudaGetSymbolAddress((void**)&rows,   g_rows);
  cudaGetSymbolAddress((void**)&tot,    g_tot);
  cudaGetSymbolAddress((void**)&part,   g_part);
  cudaGetSymbolAddress((void**)&apart,  g_apart);
  cudaGetSymbolAddress((void**)&attrAll,g_attrAll);
  cudaGetSymbolAddress((void**)&sp01,   g_sp01);
  cudaGetSymbolAddress((void**)&attv,   g_att);
  cudaGetSymbolAddress((void**)&c256,   g_c256);
  cudaGetSymbolAddress((void**)&s256,   g_s256);
  cudaGetSymbolAddress((void**)&win,    g_win);
  cudaGetSymbolAddress((void**)&invwin, g_invwin);
  cudaGetSymbolAddress((void**)&Bpack,  g_Bpack);
  cudaGetSymbolAddress((void**)&biasPack, g_biasPack);
  cudaGetSymbolAddress((void**)&Wg,     g_Wg);
  cudaGetSymbolAddress((void**)&uv,     g_u);
  cudaGetSymbolAddress((void**)&vv,     g_v);

  const int M = MROWS_;

  init_tables_k<<<1,256>>>(c256, s256, win, invwin);
  pack_k<<<KPACK_,256>>>(dec_w, dec_b, c256, s256, invwin, Bpack, biasPack);
  prep_c2_k<<<dim3(NBLK_,2),128>>>(c2w, g2g, g2b, Wg, uv, vv);
  frames_k<<<M,256>>>(audios, frames);

  // encoder: relu(frames @ enc_w + enc_b)
  gemmT<1><<<dim3(4,63),256>>>(frames, enc_w, enc_b, enc, M, 256, 256, 256,
                               nullptr, nullptr, nullptr, nullptr);
  fft_k<<<M,256>>>(frames, win, c256, s256, Re, Im, mag);
  cln_k<<<M,128>>>(enc, mag, bgam, bbet, xc);
  // bottleneck (K=385, lda=400 zero-padded)
  gemmT<0><<<dim3(4,63),256>>>(xc, bw, bbi, x, M, 256, 385, FCP_,
                               nullptr, nullptr, nullptr, nullptr);

  for (int i = 0; i < NBLK_; i++) {
    int di = 1 << (i & 7);
    gemmT<2><<<dim3(8,63),256>>>(x, c1w + (long)i*BTL_*HH_, c1b + i*HH_, y1,
                                 M, 512, 256, 256, p1 + i*HH_, nullptr, nullptr, nullptr);
    stat1_k<<<NB_*GNS_,256>>>(y1, part);
    dwconv2_k<<<(M*HH_/4 + 255)/256,256>>>(y1, y2, dwv + i*3*HH_, part,
                                           g1g + i*HH_, g1b + i*HH_, p2 + i*HH_, di);
    stat1_k<<<NB_*GNS_,256>>>(y2, part);
    gemmT<3><<<dim3(4,63),256>>>(y2, Wg + (long)i*HH_*BTL_, c2b + i*BTL_, x,
                                 M, 256, 512, 512, nullptr,
                                 uv + i*BTL_, vv + i*BTL_, part);
  }

  // separator: x @ sep_w + sep_b (N=7700)
  gemmT<0><<<dim3(121,63),256>>>(x, sw, sb, emb, M, NSEP_, 256, 256,
                                 nullptr, nullptr, nullptr, nullptr);
  attr_part_k<<<NB_*NPAIR_*ANS_,128>>>(emb, anchors, apart);
  attr_comb_k<<<NB_*NPAIR_,64>>>(apart, attrAll, sp01);
  choose_k<<<1,32>>>(sp01, attrAll, attv);
  code_k<<<M,128>>>(emb, attv, enc, Re, Im, rows);
  // fused conv-decode + iSTFT GEMM (K=514, lda=528 zero-padded)
  gemmT<0><<<dim3(4,125),256>>>(rows, Bpack, biasPack, tot, MROWS2_, 256, 514, KPACKP_,
                                nullptr, nullptr, nullptr, nullptr);
  ola_k<<<(NB_*2*LAUD_+255)/256,256>>>(tot, out);
}

// round 10
// speedup vs baseline: 1.0411x; 1.0411x over previous
#include <cuda_runtime.h>
#include <math.h>
#include <float.h>

// ---------------- problem constants ----------------
#define NB_    8
#define TT_    497
#define LAUD_  32000
#define HOP_   64
#define NFFT_  256
#define AE_    256
#define BTL_   256
#define HH_    512
#define FC_    385
#define FCP_   400        // padded stride for xc (K=385 -> 25*16)
#define NFREQ_ 129
#define EMBD_  20
#define NBLK_  32
#define NPAIR_ 15
#define KPACK_ 514
#define KPACKP_ 528       // padded stride for rows (33*16)
#define GNS_   32
#define ANS_   64
#define MROWS_ (NB_*TT_)          // 3976
#define MROWS2_ (NB_*2*TT_)       // 7952
#define NSEP_  (FC_*EMBD_)        // 7700

// ---------------- device scratch ----------------
__device__ float g_frames[MROWS_*NFFT_];
__device__ float g_enc[MROWS_*AE_];
__device__ float g_Re[MROWS_*NFREQ_];
__device__ float g_Im[MROWS_*NFREQ_];
__device__ float g_mag[MROWS_*NFREQ_];
__device__ float g_xc[MROWS_*FCP_];
__device__ float g_x[MROWS_*BTL_];
__device__ float g_y1[MROWS_*HH_];
__device__ float g_y2[MROWS_*HH_];
__device__ float g_emb[(long)MROWS_*NSEP_];
__device__ float g_rows[(long)MROWS2_*KPACKP_];
__device__ float g_tot[MROWS2_*NFFT_];
__device__ double g_part[NB_*GNS_*2];
__device__ float g_apart[NB_*NPAIR_*ANS_*42];
__device__ float g_attrAll[NB_*NPAIR_*40];
__device__ float g_sp01[NB_*NPAIR_];
__device__ float g_att[NB_*40];
__device__ float g_c256[256], g_s256[256], g_win[256], g_invwin[256];
__device__ float g_Bpack[KPACK_*256], g_biasPack[256];
__device__ float g_Wg[NBLK_*HH_*BTL_];
__device__ float g_u[NBLK_*BTL_], g_v[NBLK_*BTL_];

__constant__ int d_combs[NPAIR_][2] = {
  {0,1},{0,2},{0,3},{0,4},{0,5},{1,2},{1,3},{1,4},{1,5},
  {2,3},{2,4},{2,5},{3,4},{3,5},{4,5}
};

// ---------------- tf32 helpers ----------------
__device__ __forceinline__ void split_tf32(float x, float& h, float& l) {
  unsigned hu;
  asm("cvt.rna.tf32.f32 %0, %1;" : "=r"(hu) : "f"(x));
  h = __uint_as_float(hu);
  float r = x - h;
  unsigned lu;
  asm("cvt.rna.tf32.f32 %0, %1;" : "=r"(lu) : "f"(r));
  l = __uint_as_float(lu);
}
__device__ __forceinline__ void split4(const float4& v, float4& h, float4& l) {
  split_tf32(v.x, h.x, l.x);
  split_tf32(v.y, h.y, l.y);
  split_tf32(v.z, h.z, l.z);
  split_tf32(v.w, h.w, l.w);
}
__device__ __forceinline__ void mma8(float* c, const unsigned* a, const unsigned* b) {
  asm volatile(
    "mma.sync.aligned.m16n8k8.row.col.f32.tf32.tf32.f32 "
    "{%0,%1,%2,%3}, {%4,%5,%6,%7}, {%8,%9}, {%0,%1,%2,%3};\n"
    : "+f"(c[0]), "+f"(c[1]), "+f"(c[2]), "+f"(c[3])
    : "r"(a[0]), "r"(a[1]), "r"(a[2]), "r"(a[3]), "r"(b[0]), "r"(b[1]));
}

// ---------------- tables / weight prep ----------------
__global__ void init_tables_k(float* c, float* s, float* win, float* invwin) {
  int n = threadIdx.x;
  double a = 2.0 * 3.14159265358979323846 * (double)n / 256.0;
  double cv = cos(a), sv = sin(a);
  c[n] = (float)cv; s[n] = (float)sv;
  float w = (float)sqrt(0.5 - 0.5 * cv);
  win[n] = w;
  __syncthreads();
  __shared__ float dn[64];
  if (n < 64) {
    float d = 0.f;
    for (int q = 0; q < 4; q++) { float wv = win[n + 64*q]; d += wv*wv; }
    dn[n] = d;
  }
  __syncthreads();
  invwin[n] = win[n] / dn[n & 63];
}

__global__ void pack_k(const float* __restrict__ dec_w, const float* __restrict__ dec_b,
                       const float* __restrict__ c, const float* __restrict__ s,
                       const float* __restrict__ invwin,
                       float* __restrict__ Bp, float* __restrict__ biasP) {
  int k = blockIdx.x, n = threadIdx.x;
  float v;
  if (k < 256) {
    v = 0.5f * dec_w[k*256 + n];
  } else if (k < 385) {
    int j = k - 256;
    float wj = (j == 0 || j == 128) ? 1.f : 2.f;
    int m = (j * n) & 255;
    v = 0.5f * invwin[n] * wj * c[m] * (1.f/256.f);
  } else {
    int j = k - 385;
    float wj = (j == 0 || j == 128) ? 1.f : 2.f;
    int m = (j * n) & 255;
    v = -0.5f * invwin[n] * wj * s[m] * (1.f/256.f);
  }
  Bp[k*256 + n] = v;
  if (k == 0) biasP[n] = 0.5f * dec_b[n];
}

__global__ void prep_c2_k(const float* __restrict__ c2w, const float* __restrict__ g2g,
                          const float* __restrict__ g2b,
                          float* __restrict__ Wg, float* __restrict__ u, float* __restrict__ v) {
  int i = blockIdx.x;
  int n = blockIdx.y * 128 + threadIdx.x;
  const float* W  = c2w + (long)i*HH_*BTL_;
  const float* gg = g2g + i*HH_;
  const float* bb = g2b + i*HH_;
  float* Wo = Wg + (long)i*HH_*BTL_;
  float au = 0.f, av = 0.f;
  for (int k = 0; k < HH_; k++) {
    float w = W[k*BTL_ + n];
    float wg = gg[k] * w;
    au = fmaf(bb[k], w, au);
    av += wg;
    Wo[k*BTL_ + n] = wg;
  }
  u[i*BTL_ + n] = au;
  v[i*BTL_ + n] = av;
}

// ---------------- framing ----------------
__global__ void frames_k(const float* __restrict__ aud, float* __restrict__ frames) {
  int bt = blockIdx.x, n = threadIdx.x;
  int b = bt / TT_, t = bt % TT_;
  int off = b * 2 * LAUD_ + t * HOP_ + n;
  frames[bt * NFFT_ + n] = aud[off] + aud[off + LAUD_];
}

// ---------------- rDFT ----------------
__global__ void fft_k(const float* __restrict__ frames, const float* __restrict__ win,
                      const float* __restrict__ c, const float* __restrict__ s,
                      float* __restrict__ Re, float* __restrict__ Im, float* __restrict__ Mag) {
  int bt = blockIdx.x, tid = threadIdx.x;
  __shared__ float row[256], sc[256], ss[256];
  row[tid] = frames[bt*NFFT_ + tid] * win[tid];
  sc[tid] = c[tid]; ss[tid] = s[tid];
  __syncthreads();
  if (tid < NFREQ_) {
    int j = tid;
    float re = 0.f, im = 0.f;
    int m = 0;
    #pragma unroll 8
    for (int n = 0; n < 256; n++) {
      float v = row[n];
      re = fmaf(v, sc[m], re);
      im = fmaf(-v, ss[m], im);
      m = (m + j) & 255;
    }
    Re[bt*NFREQ_ + j] = re;
    Im[bt*NFREQ_ + j] = im;
    Mag[bt*NFREQ_ + j] = sqrtf(re*re + im*im);
  }
}

// ---------------- cLN ----------------
__global__ void cln_k(const float* __restrict__ enc, const float* __restrict__ mag,
                      const float* __restrict__ gamma, const float* __restrict__ beta,
                      float* __restrict__ xc) {
  int bt = blockIdx.x, tid = threadIdx.x;
  __shared__ float vals[FC_];
  for (int f = tid; f < FC_; f += 128)
    vals[f] = (f < AE_) ? enc[bt*AE_ + f] : log1pf(mag[bt*NFREQ_ + (f - AE_)]);
  __syncthreads();
  double s = 0.0, ss = 0.0;
  for (int f = tid; f < FC_; f += 128) { double v = vals[f]; s += v; ss += v*v; }
  __shared__ double rs[128], rss[128];
  rs[tid] = s; rss[tid] = ss; __syncthreads();
  for (int o = 64; o > 0; o >>= 1) {
    if (tid < o) { rs[tid] += rs[tid+o]; rss[tid] += rss[tid+o]; }
    __syncthreads();
  }
  __shared__ float mS, iS;
  if (tid == 0) {
    double m = rs[0] / FC_;
    double var = rss[0] / FC_ - m*m;
    mS = (float)m; iS = (float)rsqrt(var + 1e-12);
  }
  __syncthreads();
  for (int f = tid; f < FC_; f += 128)
    xc[bt*FCP_ + f] = (vals[f] - mS) * iS * gamma[f] + beta[f];
  for (int f = FC_ + tid; f < FCP_; f += 128)
    xc[bt*FCP_ + f] = 0.f;
}

// ---------------- tf32 tensor-core GEMM v5 (templated BN) ----------------
// Block 64xBN x16, 256 threads = 8 warps (2M x 4N), warp tile 32 x (BN/4).
// Raw fp32 global loads; split to tf32 (hi,lo) ONCE at smem-store time into
// XOR-swizzled Ah/Al/Bh/Bl (conflict-free fragment LDS). Inner loop: pure
// LDS + MMA, 3xTF32 compensation with TERM-MAJOR ordering (dependent MMAs
// on an accumulator are NT*2 apart -> latency hidden without extra regs).
// PTX m16n8k8.tf32 fragments (g=lane>>2, t=lane&3):
//   A: a0=A[g][t] a1=A[g+8][t] a2=A[g][t+4] a3=A[g+8][t+4]
//   B: b0=B[t][n] b1=B[t+4][n]
//   C: c0=[g][2t] c1=[g][2t+1] c2=[g+8][2t] c3=[g+8][2t+1]
// Requires lda >= ceil(K/16)*16 with zero padding in A rows beyond K.
// EPI: 0 none, 1 relu, 2 prelu(col), 3 residual-add + per-batch gLN affine
template<int EPI, int BN>
__global__ __launch_bounds__(256)
void gemmT(const float* __restrict__ A, const float* __restrict__ Bm,
           const float* __restrict__ bias, float* __restrict__ C,
           int M, int N, int K, int lda,
           const float* __restrict__ prelu,
           const float* __restrict__ uvec, const float* __restrict__ vvec,
           const double* __restrict__ part) {
  constexpr int BM = 64, BK = 16;
  constexpr int NT = BN / 32;          // n-frags per warp: 4 (BN=128) or 2 (BN=64)
  constexpr int BQ = BN / 4;           // float4 per B row
  constexpr int BPASS = (BK * BQ) / 256;  // B-load passes: 2 or 1
  __shared__ float Ah[2][BM][BK], Al[2][BM][BK];   // col k ^ (4*((m>>1)&3))
  __shared__ float Bh[2][BK][BN], Bl[2][BK][BN];   // col n ^ (8*(k&3))
  __shared__ float s_m[8], s_i[8];

  const int tid = threadIdx.x;
  if (EPI == 3 && tid < 8) {
    double sm = 0.0, ss = 0.0;
    for (int q = 0; q < GNS_; q++) {
      sm += part[(tid*GNS_+q)*2];
      ss += part[(tid*GNS_+q)*2 + 1];
    }
    const double pb = (double)(TT_*HH_);
    double mm = sm / pb;
    s_m[tid] = (float)mm;
    s_i[tid] = (float)rsqrt(ss / pb - mm*mm + 1e-12);
  }

  const int row0 = blockIdx.y * BM, col0 = blockIdx.x * BN;
  const int wid = tid >> 5, lane = tid & 31;
  const int g = lane >> 2, t = lane & 3;
  const int m0w = (wid >> 2) * 32;        // 0 or 32
  const int n0w = (wid & 3) * (8 * NT);   // warp N offset

  float acc[2][NT][4];
  #pragma unroll
  for (int i = 0; i < 2; i++)
    #pragma unroll
    for (int j = 0; j < NT; j++)
      #pragma unroll
      for (int q = 0; q < 4; q++) acc[i][j][q] = 0.f;

  float4 aR, bR[BPASS];
  const int am = tid >> 2, ak4 = (tid & 3) << 2;
  const int asw = ak4 ^ (4 * ((am >> 1) & 3));

  auto loadA = [&](int kt) {
    int row = row0 + am;
    float4 r = make_float4(0.f, 0.f, 0.f, 0.f);
    if (row < M) r = *(const float4*)(A + (long)row * lda + kt * BK + ak4);
    aR = r;
  };
  auto loadB = [&](int kt) {
    #pragma unroll
    for (int p = 0; p < BPASS; p++) {
      int id = tid + p * 256;
      int bk = id / BQ, bn4 = (id % BQ) * 4;
      int gk = kt * BK + bk, col = col0 + bn4;
      float4 r = make_float4(0.f, 0.f, 0.f, 0.f);
      if (gk < K) {
        const float* bp = Bm + (long)gk * N + col;
        if (col + 3 < N) r = *(const float4*)bp;
        else {
          if (col     < N) r.x = bp[0];
          if (col + 1 < N) r.y = bp[1];
          if (col + 2 < N) r.z = bp[2];
        }
      }
      bR[p] = r;
    }
  };
  auto storeT = [&](int buf) {
    float4 h4, l4;
    split4(aR, h4, l4);
    *(float4*)&Ah[buf][am][asw] = h4;
    *(float4*)&Al[buf][am][asw] = l4;
    #pragma unroll
    for (int p = 0; p < BPASS; p++) {
      int id = tid + p * 256;
      int bk = id / BQ, bn4 = (id % BQ) * 4;
      int swb = bn4 ^ (8 * (bk & 3));
      split4(bR[p], h4, l4);
      *(float4*)&Bh[buf][bk][swb] = h4;
      *(float4*)&Bl[buf][bk][swb] = l4;
    }
  };

  const int ktot = (K + BK - 1) / BK;
  loadA(0); loadB(0);
  storeT(0);
  __syncthreads();

  for (int kt = 0; kt < ktot; kt++) {
    const int buf = kt & 1;
    const bool more = (kt + 1 < ktot);
    if (more) { loadA(kt + 1); loadB(kt + 1); }

    #pragma unroll
    for (int ks = 0; ks < 2; ks++) {
      const int k1 = ks * 8 + t, k2 = k1 + 4;
      unsigned ah[2][4], al[2][4];
      #pragma unroll
      for (int mi = 0; mi < 2; mi++) {
        int rA = m0w + mi * 16 + g;
        int sw = 4 * ((rA >> 1) & 3);       // same for rA and rA+8
        ah[mi][0] = __float_as_uint(Ah[buf][rA    ][k1 ^ sw]);
        ah[mi][1] = __float_as_uint(Ah[buf][rA + 8][k1 ^ sw]);
        ah[mi][2] = __float_as_uint(Ah[buf][rA    ][k2 ^ sw]);
        ah[mi][3] = __float_as_uint(Ah[buf][rA + 8][k2 ^ sw]);
        al[mi][0] = __float_as_uint(Al[buf][rA    ][k1 ^ sw]);
        al[mi][1] = __float_as_uint(Al[buf][rA + 8][k1 ^ sw]);
        al[mi][2] = __float_as_uint(Al[buf][rA    ][k2 ^ sw]);
        al[mi][3] = __float_as_uint(Al[buf][rA + 8][k2 ^ sw]);
      }
      unsigned bh[NT][2], bl[NT][2];
      const int bsw = 8 * (k1 & 3);         // k1&3 == k2&3
      #pragma unroll
      for (int ni = 0; ni < NT; ni++) {
        int cn = (n0w + ni * 8 + g) ^ bsw;
        bh[ni][0] = __float_as_uint(Bh[buf][k1][cn]);
        bh[ni][1] = __float_as_uint(Bh[buf][k2][cn]);
        bl[ni][0] = __float_as_uint(Bl[buf][k1][cn]);
        bl[ni][1] = __float_as_uint(Bl[buf][k2][cn]);
      }
      // term-major: dependent MMAs on the same acc are 2*NT apart
      #pragma unroll
      for (int mi = 0; mi < 2; mi++)
        #pragma unroll
        for (int ni = 0; ni < NT; ni++)
          mma8(acc[mi][ni], ah[mi], bl[ni]);
      #pragma unroll
      for (int mi = 0; mi < 2; mi++)
        #pragma unroll
        for (int ni = 0; ni < NT; ni++)
          mma8(acc[mi][ni], al[mi], bh[ni]);
      #pragma unroll
      for (int mi = 0; mi < 2; mi++)
        #pragma unroll
        for (int ni = 0; ni < NT; ni++)
          mma8(acc[mi][ni], ah[mi], bh[ni]);
    }

    if (more) { storeT(buf ^ 1); __syncthreads(); }
  }

  // epilogue: c-fragment row = g + ii*8, col = 2t + jj
  #pragma unroll
  for (int mi = 0; mi < 2; mi++) {
    #pragma unroll
    for (int ii = 0; ii < 2; ii++) {
      int row = row0 + m0w + mi * 16 + g + ii * 8;
      if (row >= M) continue;
      float si = 1.f, smn = 0.f;
      if (EPI == 3) { int b = row / TT_; si = s_i[b]; smn = s_m[b]; }
      float* crow = C + (long)row * N;
      #pragma unroll
      for (int ni = 0; ni < NT; ni++) {
        #pragma unroll
        for (int jj = 0; jj < 2; jj++) {
          int cc = col0 + n0w + ni * 8 + 2 * t + jj;
          if (cc >= N) continue;
          float vx = acc[mi][ni][ii * 2 + jj];
          if (EPI == 0) vx += bias[cc];
          if (EPI == 1) { vx += bias[cc]; vx = fmaxf(vx, 0.f); }
          if (EPI == 2) { vx += bias[cc]; vx = fmaxf(vx, 0.f) + prelu[cc] * fminf(vx, 0.f); }
          if (EPI == 3) vx = crow[cc] + si * vx + (uvec[cc] - smn * si * vvec[cc]) + bias[cc];
          crow[cc] = vx;
        }
      }
    }
  }
}

// ---------------- gLN partial stats ----------------
__global__ void stat1_k(const float* __restrict__ x, double* __restrict__ part) {
  int b = blockIdx.x >> 5, s = blockIdx.x & 31;
  const int tot4 = TT_*HH_/4;
  const int chunk4 = tot4 / GNS_;
  int st = s * chunk4, en = st + chunk4;
  const float4* x4 = (const float4*)(x + (long)b * TT_ * HH_);
  double sm = 0.0, ss = 0.0;
  for (int i = st + threadIdx.x; i < en; i += 256) {
    float4 v = x4[i];
    sm += (double)v.x + v.y + v.z + v.w;
    ss += (double)v.x*v.x + (double)v.y*v.y + (double)v.z*v.z + (double)v.w*v.w;
  }
  __shared__ double rs[256], rss[256];
  int tid = threadIdx.x;
  rs[tid] = sm; rss[tid] = ss; __syncthreads();
  for (int o = 128; o > 0; o >>= 1) {
    if (tid < o) { rs[tid] += rs[tid+o]; rss[tid] += rss[tid+o]; }
    __syncthreads();
  }
  if (tid == 0) { part[(b*GNS_+s)*2] = rs[0]; part[(b*GNS_+s)*2+1] = rss[0]; }
}

// ---------------- dwconv ----------------
__global__ __launch_bounds__(256)
void dwconv2_k(const float* __restrict__ y1, float* __restrict__ y2,
               const float* __restrict__ w, const double* __restrict__ part,
               const float* __restrict__ g, const float* __restrict__ be,
               const float* __restrict__ p2, int d) {
  __shared__ float s_m[8], s_i[8];
  int tid = threadIdx.x;
  if (tid < 8) {
    double sm = 0.0, ss = 0.0;
    for (int q = 0; q < GNS_; q++) {
      sm += part[(tid*GNS_+q)*2];
      ss += part[(tid*GNS_+q)*2 + 1];
    }
    const double pb = (double)(TT_*HH_);
    double mm = sm / pb;
    s_m[tid] = (float)mm;
    s_i[tid] = (float)rsqrt(ss / pb - mm*mm + 1e-12);
  }
  __syncthreads();
  int idx4 = blockIdx.x * 256 + tid;
  if (idx4 >= MROWS_ * HH_ / 4) return;
  int c4 = (idx4 & 127) << 2;
  int bt = idx4 >> 7;
  int t = bt % TT_, b = bt / TT_;
  float m = s_m[b], si = s_i[b];
  float4 gg = *(const float4*)(g + c4);
  float4 bb = *(const float4*)(be + c4);
  float4 pp = *(const float4*)(p2 + c4);
  float4 acc = make_float4(0.f,0.f,0.f,0.f);
  #pragma unroll
  for (int k = 0; k < 3; k++) {
    int tt = t + (k - 1) * d;
    if (tt >= 0 && tt < TT_) {
      float4 v = *(const float4*)(y1 + ((long)(b*TT_ + tt))*HH_ + c4);
      float4 wv = *(const float4*)(w + k*HH_ + c4);
      acc.x = fmaf(wv.x, (v.x - m)*si*gg.x + bb.x, acc.x);
      acc.y = fmaf(wv.y, (v.y - m)*si*gg.y + bb.y, acc.y);
      acc.z = fmaf(wv.z, (v.z - m)*si*gg.z + bb.z, acc.z);
      acc.w = fmaf(wv.w, (v.w - m)*si*gg.w + bb.w, acc.w);
    }
  }
  float4 o;
  o.x = fmaxf(acc.x, 0.f) + pp.x * fminf(acc.x, 0.f);
  o.y = fmaxf(acc.y, 0.f) + pp.y * fminf(acc.y, 0.f);
  o.z = fmaxf(acc.z, 0.f) + pp.z * fminf(acc.z, 0.f);
  o.w = fmaxf(acc.w, 0.f) + pp.w * fminf(acc.w, 0.f);
  *(float4*)(y2 + (long)idx4*4) = o;
}

// ---------------- attractor ----------------
__device__ __forceinline__ float warp_sum(float x) {
  #pragma unroll
  for (int o = 16; o > 0; o >>= 1) x += __shfl_down_sync(0xffffffffu, x, o);
  return x;
}

__global__ __launch_bounds__(128)
void attr_part_k(const float* __restrict__ emb, const float* __restrict__ anchors,
                 float* __restrict__ part) {
  int bp = blockIdx.x % (NB_*NPAIR_);
  int s  = blockIdx.x / (NB_*NPAIR_);
  int b = bp / NPAIR_, p = bp % NPAIR_;
  int tid = threadIdx.x;
  __shared__ float a0[EMBD_], a1[EMBD_];
  if (tid < EMBD_) {
    a0[tid] = anchors[d_combs[p][0] * EMBD_ + tid];
    a1[tid] = anchors[d_combs[p][1] * EMBD_ + tid];
  }
  __syncthreads();
  const int rows = TT_ * FC_;
  int chunk = (rows + ANS_ - 1) / ANS_;
  int st = s * chunk, en = min(rows, st + chunk);
  float num0[EMBD_], sev[EMBD_];
  #pragma unroll
  for (int i = 0; i < EMBD_; i++) { num0[i] = 0.f; sev[i] = 0.f; }
  float den0 = 0.f;
  const float* base = emb + (long)b * rows * EMBD_;
  for (int r = st + tid; r < en; r += 128) {
    const float4* e4 = (const float4*)(base + (long)r * EMBD_);
    float ev[EMBD_];
    #pragma unroll
    for (int q = 0; q < 5; q++) {
      float4 v = e4[q];
      ev[q*4+0] = v.x; ev[q*4+1] = v.y; ev[q*4+2] = v.z; ev[q*4+3] = v.w;
    }
    float dd0 = 0.f, dd1 = 0.f;
    #pragma unroll
    for (int i = 0; i < EMBD_; i++) { dd0 = fmaf(ev[i], a0[i], dd0); dd1 = fmaf(ev[i], a1[i], dd1); }
    float s0 = 1.f / (1.f + expf(dd1 - dd0));
    den0 += s0;
    #pragma unroll
    for (int i = 0; i < EMBD_; i++) { num0[i] = fmaf(s0, ev[i], num0[i]); sev[i] += ev[i]; }
  }
  __shared__ float red[4][41];
  int lane = tid & 31, w = tid >> 5;
  den0 = warp_sum(den0);
  #pragma unroll
  for (int i = 0; i < EMBD_; i++) { num0[i] = warp_sum(num0[i]); sev[i] = warp_sum(sev[i]); }
  if (lane == 0) {
    red[w][0] = den0;
    #pragma unroll
    for (int i = 0; i < EMBD_; i++) { red[w][1+i] = num0[i]; red[w][21+i] = sev[i]; }
  }
  __syncthreads();
  if (tid < 41) {
    float a = red[0][tid] + red[1][tid] + red[2][tid] + red[3][tid];
    part[(bp * ANS_ + s) * 42 + tid] = a;
  }
}

__global__ void attr_comb_k(const float* __restrict__ part, float* __restrict__ attrAll,
                            float* __restrict__ sp01) {
  int bp = blockIdx.x, tid = threadIdx.x;
  __shared__ float comb[41];
  if (tid < 41) {
    double a = 0.0;
    for (int s = 0; s < ANS_; s++) a += part[(bp * ANS_ + s) * 42 + tid];
    comb[tid] = (float)a;
  }
  __syncthreads();
  __shared__ float at[40];
  if (tid < 40) {
    int c = tid / EMBD_, e = tid % EMBD_;
    float den0 = comb[0];
    float den1 = (float)(TT_ * FC_) - den0;
    float val;
    if (c == 0) val = comb[1 + e] / den0;
    else        val = (comb[21 + e] - comb[1 + e]) / den1;
    at[tid] = val;
    attrAll[bp * 40 + tid] = val;
  }
  __syncthreads();
  if (tid == 0) {
    float s = 0.f;
    for (int e = 0; e < EMBD_; e++) s += at[e] * at[EMBD_ + e];
    sp01[bp] = s;
  }
}

__global__ void choose_k(const float* __restrict__ sp01, const float* __restrict__ attrAll,
                         float* __restrict__ attract) {
  int b = threadIdx.x;
  if (b >= NB_) return;
  float best = sp01[b * NPAIR_];
  int bi = 0;
  for (int p = 1; p < NPAIR_; p++) {
    float v = sp01[b * NPAIR_ + p];
    if (v < best) { best = v; bi = p; }
  }
  for (int k = 0; k < 40; k++)
    attract[b * 40 + k] = attrAll[(b * NPAIR_ + bi) * 40 + k];
}

// ---------------- code rows ----------------
__global__ __launch_bounds__(128)
void code_k(const float* __restrict__ emb, const float* __restrict__ attract,
            const float* __restrict__ enc, const float* __restrict__ Re,
            const float* __restrict__ Im, float* __restrict__ rows) {
  int bt = blockIdx.x, tid = threadIdx.x;
  int b = bt / TT_, t = bt % TT_;
  __shared__ float at[40];
  if (tid < 40) at[tid] = attract[b * 40 + tid];
  __syncthreads();
  long r0 = ((long)(b * 2 + 0) * TT_ + t) * KPACKP_;
  long r1 = ((long)(b * 2 + 1) * TT_ + t) * KPACKP_;
  for (int f = tid; f < FC_; f += 128) {
    const float4* e4 = (const float4*)(emb + ((long)bt * FC_ + f) * EMBD_);
    float l0 = 0.f, l1 = 0.f;
    #pragma unroll
    for (int q = 0; q < 5; q++) {
      float4 v = e4[q];
      l0 = fmaf(v.x, at[q*4+0], l0); l0 = fmaf(v.y, at[q*4+1], l0);
      l0 = fmaf(v.z, at[q*4+2], l0); l0 = fmaf(v.w, at[q*4+3], l0);
      l1 = fmaf(v.x, at[20+q*4+0], l1); l1 = fmaf(v.y, at[20+q*4+1], l1);
      l1 = fmaf(v.z, at[20+q*4+2], l1); l1 = fmaf(v.w, at[20+q*4+3], l1);
    }
    if (f < AE_) {
      float fe = enc[bt * AE_ + f];
      rows[r0 + f] = l0 * fe;
      rows[r1 + f] = l1 * fe;
    } else {
      int j = f - AE_;
      float re = Re[bt * NFREQ_ + j], im = Im[bt * NFREQ_ + j];
      rows[r0 + 256 + j] = l0 * re;
      rows[r0 + 385 + j] = l0 * im;
      rows[r1 + 256 + j] = l1 * re;
      rows[r1 + 385 + j] = l1 * im;
    }
  }
  if (tid < KPACKP_ - KPACK_) {
    rows[r0 + KPACK_ + tid] = 0.f;
    rows[r1 + KPACK_ + tid] = 0.f;
  }
}

// ---------------- overlap-add ----------------
__global__ void ola_k(const float* __restrict__ tot, float* __restrict__ out) {
  int idx = blockIdx.x * blockDim.x + threadIdx.x;
  if (idx >= NB_ * 2 * LAUD_) return;
  int l = idx % LAUD_;
  int bc = idx / LAUD_;
  int tlo = (l >= NFFT_) ? ((l - NFFT_) >> 6) + 1 : 0;
  int thi = min(TT_ - 1, l >> 6);
  float acc = 0.f;
  for (int t = tlo; t <= thi; t++)
    acc += tot[((long)bc * TT_ + t) * NFFT_ + (l - (t << 6))];
  out[idx] = acc;
}

// ---------------- host orchestration ----------------
extern "C" void kernel_launch(void* const* d_in, const int* in_sizes, int n_in,
                              void* d_out, int out_size) {
  const float* audios = (const float*)d_in[0];
  const float* enc_w  = (const float*)d_in[1];
  const float* enc_b  = (const float*)d_in[2];
  const float* bgam   = (const float*)d_in[3];
  const float* bbet   = (const float*)d_in[4];
  const float* bw     = (const float*)d_in[5];
  const float* bbi    = (const float*)d_in[6];
  const float* c1w    = (const float*)d_in[7];
  const float* c1b    = (const float*)d_in[8];
  const float* p1     = (const float*)d_in[9];
  const float* g1g    = (const float*)d_in[10];
  const float* g1b    = (const float*)d_in[11];
  const float* dwv    = (const float*)d_in[12];
  const float* p2     = (const float*)d_in[13];
  const float* g2g    = (const float*)d_in[14];
  const float* g2b    = (const float*)d_in[15];
  const float* c2w    = (const float*)d_in[16];
  const float* c2b    = (const float*)d_in[17];
  const float* sw     = (const float*)d_in[18];
  const float* sb     = (const float*)d_in[19];
  const float* anchors= (const float*)d_in[20];
  const float* dec_w  = (const float*)d_in[21];
  const float* dec_b  = (const float*)d_in[22];
  float* out = (float*)d_out;

  float *frames,*enc,*Re,*Im,*mag,*xc,*x,*y1,*y2,*emb,*rows,*tot;
  float *apart,*attrAll,*sp01,*attv;
  float *c256,*s256,*win,*invwin,*Bpack,*biasPack,*Wg,*uv,*vv;
  double *part;
  cudaGetSymbolAddress((void**)&frames, g_frames);
  cudaGetSymbolAddress((void**)&enc,    g_enc);
  cudaGetSymbolAddress((void**)&Re,     g_Re);
  cudaGetSymbolAddress((void**)&Im,     g_Im);
  cudaGetSymbolAddress((void**)&mag,    g_mag);
  cudaGetSymbolAddress((void**)&xc,     g_xc);
  cudaGetSymbolAddress((void**)&x,      g_x);
  cudaGetSymbolAddress((void**)&y1,     g_y1);
  cudaGetSymbolAddress((void**)&y2,     g_y2);
  cudaGetSymbolAddress((void**)&emb,    g_emb);
  cudaGetSymbolAddress((void**)&rows,   g_rows);
  cudaGetSymbolAddress((void**)&tot,    g_tot);
  cudaGetSymbolAddress((void**)&part,   g_part);
  cudaGetSymbolAddress((void**)&apart,  g_apart);
  cudaGetSymbolAddress((void**)&attrAll,g_attrAll);
  cudaGetSymbolAddress((void**)&sp01,   g_sp01);
  cudaGetSymbolAddress((void**)&attv,   g_att);
  cudaGetSymbolAddress((void**)&c256,   g_c256);
  cudaGetSymbolAddress((void**)&s256,   g_s256);
  cudaGetSymbolAddress((void**)&win,    g_win);
  cudaGetSymbolAddress((void**)&invwin, g_invwin);
  cudaGetSymbolAddress((void**)&Bpack,  g_Bpack);
  cudaGetSymbolAddress((void**)&biasPack, g_biasPack);
  cudaGetSymbolAddress((void**)&Wg,     g_Wg);
  cudaGetSymbolAddress((void**)&uv,     g_u);
  cudaGetSymbolAddress((void**)&vv,     g_v);

  const int M = MROWS_;

  init_tables_k<<<1,256>>>(c256, s256, win, invwin);
  pack_k<<<KPACK_,256>>>(dec_w, dec_b, c256, s256, invwin, Bpack, biasPack);
  prep_c2_k<<<dim3(NBLK_,2),128>>>(c2w, g2g, g2b, Wg, uv, vv);
  frames_k<<<M,256>>>(audios, frames);

  // encoder: relu(frames @ enc_w + enc_b)  (N=256 -> BN=64, grid 252)
  gemmT<1,64><<<dim3(4,63),256>>>(frames, enc_w, enc_b, enc, M, 256, 256, 256,
                                  nullptr, nullptr, nullptr, nullptr);
  fft_k<<<M,256>>>(frames, win, c256, s256, Re, Im, mag);
  cln_k<<<M,128>>>(enc, mag, bgam, bbet, xc);
  // bottleneck (K=385, lda=400 zero-padded)
  gemmT<0,64><<<dim3(4,63),256>>>(xc, bw, bbi, x, M, 256, 385, FCP_,
                                  nullptr, nullptr, nullptr, nullptr);

  for (int i = 0; i < NBLK_; i++) {
    int di = 1 << (i & 7);
    // N=512 -> BN=128, warp tile 32x32, grid 252
    gemmT<2,128><<<dim3(4,63),256>>>(x, c1w + (long)i*BTL_*HH_, c1b + i*HH_, y1,
                                     M, 512, 256, 256, p1 + i*HH_, nullptr, nullptr, nullptr);
    stat1_k<<<NB_*GNS_,256>>>(y1, part);
    dwconv2_k<<<(M*HH_/4 + 255)/256,256>>>(y1, y2, dwv + i*3*HH_, part,
                                           g1g + i*HH_, g1b + i*HH_, p2 + i*HH_, di);
    stat1_k<<<NB_*GNS_,256>>>(y2, part);
    // N=256 -> BN=64, grid 252
    gemmT<3,64><<<dim3(4,63),256>>>(y2, Wg + (long)i*HH_*BTL_, c2b + i*BTL_, x,
                                    M, 256, 512, 512, nullptr,
                                    uv + i*BTL_, vv + i*BTL_, part);
  }

  // separator: x @ sep_w + sep_b (N=7700 -> BN=128)
  gemmT<0,128><<<dim3(61,63),256>>>(x, sw, sb, emb, M, NSEP_, 256, 256,
                                    nullptr, nullptr, nullptr, nullptr);
  attr_part_k<<<NB_*NPAIR_*ANS_,128>>>(emb, anchors, apart);
  attr_comb_k<<<NB_*NPAIR_,64>>>(apart, attrAll, sp01);
  choose_k<<<1,32>>>(sp01, attrAll, attv);
  code_k<<<M,128>>>(emb, attv, enc, Re, Im, rows);
  // fused conv-decode + iSTFT GEMM (K=514, lda=528 zero-padded, N=256 -> BN=64)
  gemmT<0,64><<<dim3(4,125),256>>>(rows, Bpack, biasPack, tot, MROWS2_, 256, 514, KPACKP_,
                                   nullptr, nullptr, nullptr, nullptr);
  ola_k<<<(NB_*2*LAUD_+255)/256,256>>>(tot, out);
}

// round 11
// speedup vs baseline: 1.5269x; 1.4666x over previous
#include <cuda_runtime.h>
#include <math.h>
#include <float.h>

// ---------------- problem constants ----------------
#define NB_    8
#define TT_    497
#define LAUD_  32000
#define HOP_   64
#define NFFT_  256
#define AE_    256
#define BTL_   256
#define HH_    512
#define FC_    385
#define FCP_   400        // padded stride for xc (K=385 -> 25*16)
#define NFREQ_ 129
#define EMBD_  20
#define NBLK_  32
#define NPAIR_ 15
#define KPACK_ 514
#define KPACKP_ 528       // padded stride for rows (33*16)
#define ANS_   64
#define MROWS_ (NB_*TT_)          // 3976
#define MROWS2_ (NB_*2*TT_)       // 7952
#define NSEP_  (FC_*EMBD_)        // 7700

// ---------------- device scratch ----------------
__device__ float g_frames[MROWS_*NFFT_];
__device__ float g_enc[MROWS_*AE_];
__device__ float g_Re[MROWS_*NFREQ_];
__device__ float g_Im[MROWS_*NFREQ_];
__device__ float g_mag[MROWS_*NFREQ_];
__device__ float g_xc[MROWS_*FCP_];
__device__ float g_x[MROWS_*BTL_];
__device__ float g_y1[MROWS_*HH_];
__device__ float g_y2[MROWS_*HH_];
__device__ float g_emb[(long)MROWS_*NSEP_];
__device__ float g_rows[(long)MROWS2_*KPACKP_];
__device__ float g_tot[MROWS2_*NFFT_];
// per-iteration gLN accumulators: slot = 2*i (y1 stats) or 2*i+1 (y2 stats)
// layout: dstat[slot*16 + b*2 + {0:sum,1:sumsq}]
__device__ double g_dstat[NBLK_*2*16];
__device__ float g_apart[NB_*NPAIR_*ANS_*42];
__device__ float g_attrAll[NB_*NPAIR_*40];
__device__ float g_sp01[NB_*NPAIR_];
__device__ float g_att[NB_*40];
__device__ float g_c256[256], g_s256[256], g_win[256], g_invwin[256];
__device__ float g_Bpack[KPACK_*256], g_biasPack[256];
__device__ float g_Wg[NBLK_*HH_*BTL_];
__device__ float g_u[NBLK_*BTL_], g_v[NBLK_*BTL_];

__constant__ int d_combs[NPAIR_][2] = {
  {0,1},{0,2},{0,3},{0,4},{0,5},{1,2},{1,3},{1,4},{1,5},
  {2,3},{2,4},{2,5},{3,4},{3,5},{4,5}
};

// ---------------- tables (also zeroes the stat accumulators) ----------------
__global__ void init_tables_k(float* c, float* s, float* win, float* invwin,
                              double* dstat) {
  int n = threadIdx.x;
  double a = 2.0 * 3.14159265358979323846 * (double)n / 256.0;
  double cv = cos(a), sv = sin(a);
  c[n] = (float)cv; s[n] = (float)sv;
  float w = (float)sqrt(0.5 - 0.5 * cv);
  win[n] = w;
  // zero stat accumulators (NBLK*2*16 = 1024 doubles; 256 threads x 4)
  #pragma unroll
  for (int q = 0; q < 4; q++) dstat[n + q*256] = 0.0;
  __syncthreads();
  __shared__ float dn[64];
  if (n < 64) {
    float d = 0.f;
    for (int q = 0; q < 4; q++) { float wv = win[n + 64*q]; d += wv*wv; }
    dn[n] = d;
  }
  __syncthreads();
  invwin[n] = win[n] / dn[n & 63];
}

__global__ void pack_k(const float* __restrict__ dec_w, const float* __restrict__ dec_b,
                       const float* __restrict__ c, const float* __restrict__ s,
                       const float* __restrict__ invwin,
                       float* __restrict__ Bp, float* __restrict__ biasP) {
  int k = blockIdx.x, n = threadIdx.x;
  float v;
  if (k < 256) {
    v = 0.5f * dec_w[k*256 + n];
  } else if (k < 385) {
    int j = k - 256;
    float wj = (j == 0 || j == 128) ? 1.f : 2.f;
    int m = (j * n) & 255;
    v = 0.5f * invwin[n] * wj * c[m] * (1.f/256.f);
  } else {
    int j = k - 385;
    float wj = (j == 0 || j == 128) ? 1.f : 2.f;
    int m = (j * n) & 255;
    v = -0.5f * invwin[n] * wj * s[m] * (1.f/256.f);
  }
  Bp[k*256 + n] = v;
  if (k == 0) biasP[n] = 0.5f * dec_b[n];
}

__global__ void prep_c2_k(const float* __restrict__ c2w, const float* __restrict__ g2g,
                          const float* __restrict__ g2b,
                          float* __restrict__ Wg, float* __restrict__ u, float* __restrict__ v) {
  int i = blockIdx.x;
  int n = blockIdx.y * 128 + threadIdx.x;
  const float* W  = c2w + (long)i*HH_*BTL_;
  const float* gg = g2g + i*HH_;
  const float* bb = g2b + i*HH_;
  float* Wo = Wg + (long)i*HH_*BTL_;
  float au = 0.f, av = 0.f;
  for (int k = 0; k < HH_; k++) {
    float w = W[k*BTL_ + n];
    float wg = gg[k] * w;
    au = fmaf(bb[k], w, au);
    av += wg;
    Wo[k*BTL_ + n] = wg;
  }
  u[i*BTL_ + n] = au;
  v[i*BTL_ + n] = av;
}

// ---------------- framing ----------------
__global__ void frames_k(const float* __restrict__ aud, float* __restrict__ frames) {
  int bt = blockIdx.x, n = threadIdx.x;
  int b = bt / TT_, t = bt % TT_;
  int off = b * 2 * LAUD_ + t * HOP_ + n;
  frames[bt * NFFT_ + n] = aud[off] + aud[off + LAUD_];
}

// ---------------- rDFT ----------------
__global__ void fft_k(const float* __restrict__ frames, const float* __restrict__ win,
                      const float* __restrict__ c, const float* __restrict__ s,
                      float* __restrict__ Re, float* __restrict__ Im, float* __restrict__ Mag) {
  int bt = blockIdx.x, tid = threadIdx.x;
  __shared__ float row[256], sc[256], ss[256];
  row[tid] = frames[bt*NFFT_ + tid] * win[tid];
  sc[tid] = c[tid]; ss[tid] = s[tid];
  __syncthreads();
  if (tid < NFREQ_) {
    int j = tid;
    float re = 0.f, im = 0.f;
    int m = 0;
    #pragma unroll 8
    for (int n = 0; n < 256; n++) {
      float v = row[n];
      re = fmaf(v, sc[m], re);
      im = fmaf(-v, ss[m], im);
      m = (m + j) & 255;
    }
    Re[bt*NFREQ_ + j] = re;
    Im[bt*NFREQ_ + j] = im;
    Mag[bt*NFREQ_ + j] = sqrtf(re*re + im*im);
  }
}

// ---------------- cLN ----------------
__global__ void cln_k(const float* __restrict__ enc, const float* __restrict__ mag,
                      const float* __restrict__ gamma, const float* __restrict__ beta,
                      float* __restrict__ xc) {
  int bt = blockIdx.x, tid = threadIdx.x;
  __shared__ float vals[FC_];
  for (int f = tid; f < FC_; f += 128)
    vals[f] = (f < AE_) ? enc[bt*AE_ + f] : log1pf(mag[bt*NFREQ_ + (f - AE_)]);
  __syncthreads();
  double s = 0.0, ss = 0.0;
  for (int f = tid; f < FC_; f += 128) { double v = vals[f]; s += v; ss += v*v; }
  __shared__ double rs[128], rss[128];
  rs[tid] = s; rss[tid] = ss; __syncthreads();
  for (int o = 64; o > 0; o >>= 1) {
    if (tid < o) { rs[tid] += rs[tid+o]; rss[tid] += rss[tid+o]; }
    __syncthreads();
  }
  __shared__ float mS, iS;
  if (tid == 0) {
    double m = rs[0] / FC_;
    double var = rss[0] / FC_ - m*m;
    mS = (float)m; iS = (float)rsqrt(var + 1e-12);
  }
  __syncthreads();
  for (int f = tid; f < FC_; f += 128)
    xc[bt*FCP_ + f] = (vals[f] - mS) * iS * gamma[f] + beta[f];
  for (int f = FC_ + tid; f < FCP_; f += 128)
    xc[bt*FCP_ + f] = 0.f;
}

// ---------------- tf32 helpers ----------------
__device__ __forceinline__ void split_tf32(float x, unsigned& h, unsigned& l) {
  asm("cvt.rna.tf32.f32 %0, %1;" : "=r"(h) : "f"(x));
  float r = x - __uint_as_float(h);
  asm("cvt.rna.tf32.f32 %0, %1;" : "=r"(l) : "f"(r));
}

__device__ __forceinline__ void mma8(float* c, const unsigned* a, const unsigned* b) {
  asm volatile(
    "mma.sync.aligned.m16n8k8.row.col.f32.tf32.tf32.f32 "
    "{%0,%1,%2,%3}, {%4,%5,%6,%7}, {%8,%9}, {%0,%1,%2,%3};\n"
    : "+f"(c[0]), "+f"(c[1]), "+f"(c[2]), "+f"(c[3])
    : "r"(a[0]), "r"(a[1]), "r"(a[2]), "r"(a[3]), "r"(b[0]), "r"(b[1]));
}

__device__ __forceinline__ float wsum(float x) {
  #pragma unroll
  for (int o = 16; o > 0; o >>= 1) x += __shfl_down_sync(0xffffffffu, x, o);
  return x;
}

// ---------------- tf32 tensor-core GEMM (R6 config: in-loop splits) ----------------
// Block 64x128x16, 256 threads = 8 warps (2M x 4N), warp tile 32x32.
// Raw fp32 in XOR-swizzled smem (conflict-free); split to tf32 hi/lo at
// fragment-load time (overlaps with tensor pipe); 3xTF32 compensation.
// PTX m16n8k8.tf32 fragments (g=lane>>2, t=lane&3):
//   A: a0=A[g][t] a1=A[g+8][t] a2=A[g][t+4] a3=A[g+8][t+4]
//   B: b0=B[t][n] b1=B[t+4][n]
//   C: c0=[g][2t] c1=[g][2t+1] c2=[g+8][2t] c3=[g+8][2t+1]
// EPI: 0 none, 1 relu, 2 prelu(col), 3 residual-add + per-batch gLN affine
// STAT: accumulate per-batch (sum, sumsq) of written C values into dstat
//       (fp64 atomicAdd, one per block per component).
template<int EPI, bool STAT>
__global__ __launch_bounds__(256)
void gemmT(const float* __restrict__ A, const float* __restrict__ Bm,
           const float* __restrict__ bias, float* __restrict__ C,
           int M, int N, int K, int lda,
           const float* __restrict__ prelu,
           const float* __restrict__ uvec, const float* __restrict__ vvec,
           const double* __restrict__ part, double* __restrict__ dstat) {
  constexpr int BM = 64, BN = 128, BK = 16;
  __shared__ float As[2][BM][BK];    // col k ^ (4*((m>>1)&3))
  __shared__ float Bs[2][BK][BN];    // col n ^ (8*(k&3))
  __shared__ float s_m[8], s_i[8];
  __shared__ double wred[8][4];

  const int tid = threadIdx.x;
  if (EPI == 3 && tid < 8) {
    const double pb = (double)(TT_*HH_);
    double mm = part[tid*2] / pb;
    s_m[tid] = (float)mm;
    s_i[tid] = (float)rsqrt(part[tid*2+1] / pb - mm*mm + 1e-12);
  }

  const int row0 = blockIdx.y * BM, col0 = blockIdx.x * BN;
  const int wid = tid >> 5, lane = tid & 31;
  const int g = lane >> 2, t = lane & 3;
  const int m0w = (wid >> 2) * 32;      // 0 or 32
  const int n0w = (wid & 3) * 32;       // 0,32,64,96

  float acc[2][4][4];
  #pragma unroll
  for (int i = 0; i < 2; i++)
    #pragma unroll
    for (int j = 0; j < 4; j++)
      #pragma unroll
      for (int q = 0; q < 4; q++) acc[i][j][q] = 0.f;

  float4 aR, bR[2];
  const int am = tid >> 2, ak4 = (tid & 3) << 2;
  const int asw = ak4 ^ (4 * ((am >> 1) & 3));

  auto loadA = [&](int kt) {
    int row = row0 + am, gk = kt * BK + ak4;
    float4 r = make_float4(0.f, 0.f, 0.f, 0.f);
    if (row < M) r = *(const float4*)(A + (long)row * lda + gk);
    aR = r;
  };
  auto loadB = [&](int kt) {
    #pragma unroll
    for (int p = 0; p < 2; p++) {
      int idx = tid + p * 256;
      int bk = idx >> 5, bn4 = (idx & 31) << 2;
      int gk = kt * BK + bk, col = col0 + bn4;
      float4 r = make_float4(0.f, 0.f, 0.f, 0.f);
      if (gk < K) {
        const float* bp = Bm + (long)gk * N + col;
        if (col + 3 < N) r = *(const float4*)bp;
        else {
          if (col     < N) r.x = bp[0];
          if (col + 1 < N) r.y = bp[1];
          if (col + 2 < N) r.z = bp[2];
        }
      }
      bR[p] = r;
    }
  };
  auto storeT = [&](int buf) {
    *(float4*)&As[buf][am][asw] = aR;
    #pragma unroll
    for (int p = 0; p < 2; p++) {
      int idx = tid + p * 256;
      int bk = idx >> 5, bn4 = (idx & 31) << 2;
      *(float4*)&Bs[buf][bk][bn4 ^ (8 * (bk & 3))] = bR[p];
    }
  };

  const int ktot = (K + BK - 1) / BK;
  loadA(0); loadB(0);
  storeT(0);
  __syncthreads();

  for (int kt = 0; kt < ktot; kt++) {
    const int buf = kt & 1;
    const bool more = (kt + 1 < ktot);
    if (more) { loadA(kt + 1); loadB(kt + 1); }

    #pragma unroll
    for (int ks = 0; ks < 2; ks++) {
      const int k1 = ks * 8 + t, k2 = k1 + 4;
      unsigned ah[2][4], al[2][4];
      #pragma unroll
      for (int mi = 0; mi < 2; mi++) {
        int rA = m0w + mi * 16 + g;
        int sw = 4 * ((rA >> 1) & 3);       // same for rA and rA+8
        float r0 = As[buf][rA    ][k1 ^ sw];
        float r1 = As[buf][rA + 8][k1 ^ sw];
        float r2 = As[buf][rA    ][k2 ^ sw];
        float r3 = As[buf][rA + 8][k2 ^ sw];
        split_tf32(r0, ah[mi][0], al[mi][0]);
        split_tf32(r1, ah[mi][1], al[mi][1]);
        split_tf32(r2, ah[mi][2], al[mi][2]);
        split_tf32(r3, ah[mi][3], al[mi][3]);
      }
      unsigned bh[4][2], bl[4][2];
      const int bsw = 8 * (k1 & 3);
      #pragma unroll
      for (int ni = 0; ni < 4; ni++) {
        int cn = (n0w + ni * 8 + g) ^ bsw;
        float r0 = Bs[buf][k1][cn];
        float r1 = Bs[buf][k2][cn];
        split_tf32(r0, bh[ni][0], bl[ni][0]);
        split_tf32(r1, bh[ni][1], bl[ni][1]);
      }
      #pragma unroll
      for (int mi = 0; mi < 2; mi++)
        #pragma unroll
        for (int ni = 0; ni < 4; ni++) {
          mma8(acc[mi][ni], ah[mi], bl[ni]);
          mma8(acc[mi][ni], al[mi], bh[ni]);
          mma8(acc[mi][ni], ah[mi], bh[ni]);
        }
    }

    if (more) { storeT(buf ^ 1); __syncthreads(); }
  }

  // epilogue: c-fragment row = g + ii*8, col = 2t + jj
  const int bLo = row0 / TT_;
  const int rsplit = (bLo + 1) * TT_;
  float sLo = 0.f, qLo = 0.f, sHi = 0.f, qHi = 0.f;
  #pragma unroll
  for (int mi = 0; mi < 2; mi++) {
    #pragma unroll
    for (int ii = 0; ii < 2; ii++) {
      int row = row0 + m0w + mi * 16 + g + ii * 8;
      if (row >= M) continue;
      float si = 1.f, smn = 0.f;
      if (EPI == 3) { int b = row / TT_; si = s_i[b]; smn = s_m[b]; }
      float* crow = C + (long)row * N;
      float rs = 0.f, rq = 0.f;
      #pragma unroll
      for (int ni = 0; ni < 4; ni++) {
        #pragma unroll
        for (int jj = 0; jj < 2; jj++) {
          int cc = col0 + n0w + ni * 8 + 2 * t + jj;
          if (cc >= N) continue;
          float vx = acc[mi][ni][ii * 2 + jj];
          if (EPI == 0) vx += bias[cc];
          if (EPI == 1) { vx += bias[cc]; vx = fmaxf(vx, 0.f); }
          if (EPI == 2) { vx += bias[cc]; vx = fmaxf(vx, 0.f) + prelu[cc] * fminf(vx, 0.f); }
          if (EPI == 3) vx = crow[cc] + si * vx + (uvec[cc] - smn * si * vvec[cc]) + bias[cc];
          crow[cc] = vx;
          if (STAT) { rs += vx; rq = fmaf(vx, vx, rq); }
        }
      }
      if (STAT) {
        if (row < rsplit) { sLo += rs; qLo += rq; }
        else              { sHi += rs; qHi += rq; }
      }
    }
  }
  if (STAT) {
    sLo = wsum(sLo); qLo = wsum(qLo); sHi = wsum(sHi); qHi = wsum(qHi);
    if (lane == 0) {
      wred[wid][0] = sLo; wred[wid][1] = qLo;
      wred[wid][2] = sHi; wred[wid][3] = qHi;
    }
    __syncthreads();
    if (tid < 4) {
      double a = 0.0;
      #pragma unroll
      for (int w = 0; w < 8; w++) a += wred[w][tid];
      int b = (tid < 2) ? bLo : bLo + 1;
      if (b < NB_ && a != 0.0) atomicAdd(&dstat[b*2 + (tid & 1)], a);
    }
  }
}

// ---------------- dwconv (fused y1-stat finalize + gLN + conv + prelu + y2-stat) ----
__global__ __launch_bounds__(256)
void dwconv2_k(const float* __restrict__ y1, float* __restrict__ y2,
               const float* __restrict__ w, const double* __restrict__ partA,
               double* __restrict__ dstatB,
               const float* __restrict__ g, const float* __restrict__ be,
               const float* __restrict__ p2, int d) {
  __shared__ float s_m[8], s_i[8];
  __shared__ double wred[8][2];
  int tid = threadIdx.x;
  if (tid < 8) {
    const double pb = (double)(TT_*HH_);
    double mm = partA[tid*2] / pb;
    s_m[tid] = (float)mm;
    s_i[tid] = (float)rsqrt(partA[tid*2+1] / pb - mm*mm + 1e-12);
  }
  __syncthreads();
  int idx4 = blockIdx.x * 256 + tid;     // grid covers exactly MROWS_*HH_/4
  int c4 = (idx4 & 127) << 2;
  int bt = idx4 >> 7;
  int t = bt % TT_, b = bt / TT_;
  float m = s_m[b], si = s_i[b];
  float4 gg = *(const float4*)(g + c4);
  float4 bb = *(const float4*)(be + c4);
  float4 pp = *(const float4*)(p2 + c4);
  float4 acc = make_float4(0.f,0.f,0.f,0.f);
  #pragma unroll
  for (int k = 0; k < 3; k++) {
    int tt = t + (k - 1) * d;
    if (tt >= 0 && tt < TT_) {
      float4 v = *(const float4*)(y1 + ((long)(b*TT_ + tt))*HH_ + c4);
      float4 wv = *(const float4*)(w + k*HH_ + c4);
      acc.x = fmaf(wv.x, (v.x - m)*si*gg.x + bb.x, acc.x);
      acc.y = fmaf(wv.y, (v.y - m)*si*gg.y + bb.y, acc.y);
      acc.z = fmaf(wv.z, (v.z - m)*si*gg.z + bb.z, acc.z);
      acc.w = fmaf(wv.w, (v.w - m)*si*gg.w + bb.w, acc.w);
    }
  }
  float4 o;
  o.x = fmaxf(acc.x, 0.f) + pp.x * fminf(acc.x, 0.f);
  o.y = fmaxf(acc.y, 0.f) + pp.y * fminf(acc.y, 0.f);
  o.z = fmaxf(acc.z, 0.f) + pp.z * fminf(acc.z, 0.f);
  o.w = fmaxf(acc.w, 0.f) + pp.w * fminf(acc.w, 0.f);
  *(float4*)(y2 + (long)idx4*4) = o;

  // fused y2 stats: block spans 2 bt rows -> at most 2 batches (lo/hi)
  const int bLo = (blockIdx.x * 2) / TT_;   // batch of first bt in block (2 bt per block: 256*4/512)
  float s = o.x + o.y + o.z + o.w;
  float q = o.x*o.x + o.y*o.y + o.z*o.z + o.w*o.w;
  float sLo = (b == bLo) ? s : 0.f, qLo = (b == bLo) ? q : 0.f;
  float sHi = (b == bLo) ? 0.f : s, qHi = (b == bLo) ? 0.f : q;
  sLo = wsum(sLo); qLo = wsum(qLo); sHi = wsum(sHi); qHi = wsum(qHi);
  int lane = tid & 31, wid = tid >> 5;
  if (lane == 0) { wred[wid][0] = sLo; wred[wid][1] = qLo; }
  __syncthreads();
  // hi components rarely nonzero; handle via second smem pass only if needed
  __shared__ double wredH[8][2];
  if (lane == 0) { wredH[wid][0] = sHi; wredH[wid][1] = qHi; }
  __syncthreads();
  if (tid < 2) {
    double a = 0.0, ah = 0.0;
    #pragma unroll
    for (int w = 0; w < 8; w++) { a += wred[w][tid]; ah += wredH[w][tid]; }
    if (a  != 0.0) atomicAdd(&dstatB[bLo*2 + tid], a);
    int bH = bLo + 1;
    if (bH < NB_ && ah != 0.0) atomicAdd(&dstatB[bH*2 + tid], ah);
  }
}

// ---------------- attractor ----------------
__global__ __launch_bounds__(128)
void attr_part_k(const float* __restrict__ emb, const float* __restrict__ anchors,
                 float* __restrict__ part) {
  int bp = blockIdx.x % (NB_*NPAIR_);
  int s  = blockIdx.x / (NB_*NPAIR_);
  int b = bp / NPAIR_, p = bp % NPAIR_;
  int tid = threadIdx.x;
  __shared__ float a0[EMBD_], a1[EMBD_];
  if (tid < EMBD_) {
    a0[tid] = anchors[d_combs[p][0] * EMBD_ + tid];
    a1[tid] = anchors[d_combs[p][1] * EMBD_ + tid];
  }
  __syncthreads();
  const int rows = TT_ * FC_;
  int chunk = (rows + ANS_ - 1) / ANS_;
  int st = s * chunk, en = min(rows, st + chunk);
  float num0[EMBD_], sev[EMBD_];
  #pragma unroll
  for (int i = 0; i < EMBD_; i++) { num0[i] = 0.f; sev[i] = 0.f; }
  float den0 = 0.f;
  const float* base = emb + (long)b * rows * EMBD_;
  for (int r = st + tid; r < en; r += 128) {
    const float4* e4 = (const float4*)(base + (long)r * EMBD_);
    float ev[EMBD_];
    #pragma unroll
    for (int q = 0; q < 5; q++) {
      float4 v = e4[q];
      ev[q*4+0] = v.x; ev[q*4+1] = v.y; ev[q*4+2] = v.z; ev[q*4+3] = v.w;
    }
    float dd0 = 0.f, dd1 = 0.f;
    #pragma unroll
    for (int i = 0; i < EMBD_; i++) { dd0 = fmaf(ev[i], a0[i], dd0); dd1 = fmaf(ev[i], a1[i], dd1); }
    float s0 = 1.f / (1.f + expf(dd1 - dd0));
    den0 += s0;
    #pragma unroll
    for (int i = 0; i < EMBD_; i++) { num0[i] = fmaf(s0, ev[i], num0[i]); sev[i] += ev[i]; }
  }
  __shared__ float red[4][41];
  int lane = tid & 31, w = tid >> 5;
  den0 = wsum(den0);
  #pragma unroll
  for (int i = 0; i < EMBD_; i++) { num0[i] = wsum(num0[i]); sev[i] = wsum(sev[i]); }
  if (lane == 0) {
    red[w][0] = den0;
    #pragma unroll
    for (int i = 0; i < EMBD_; i++) { red[w][1+i] = num0[i]; red[w][21+i] = sev[i]; }
  }
  __syncthreads();
  if (tid < 41) {
    float a = red[0][tid] + red[1][tid] + red[2][tid] + red[3][tid];
    part[(bp * ANS_ + s) * 42 + tid] = a;
  }
}

__global__ void attr_comb_k(const float* __restrict__ part, float* __restrict__ attrAll,
                            float* __restrict__ sp01) {
  int bp = blockIdx.x, tid = threadIdx.x;
  __shared__ float comb[41];
  if (tid < 41) {
    double a = 0.0;
    for (int s = 0; s < ANS_; s++) a += part[(bp * ANS_ + s) * 42 + tid];
    comb[tid] = (float)a;
  }
  __syncthreads();
  __shared__ float at[40];
  if (tid < 40) {
    int c = tid / EMBD_, e = tid % EMBD_;
    float den0 = comb[0];
    float den1 = (float)(TT_ * FC_) - den0;
    float val;
    if (c == 0) val = comb[1 + e] / den0;
    else        val = (comb[21 + e] - comb[1 + e]) / den1;
    at[tid] = val;
    attrAll[bp * 40 + tid] = val;
  }
  __syncthreads();
  if (tid == 0) {
    float s = 0.f;
    for (int e = 0; e < EMBD_; e++) s += at[e] * at[EMBD_ + e];
    sp01[bp] = s;
  }
}

__global__ void choose_k(const float* __restrict__ sp01, const float* __restrict__ attrAll,
                         float* __restrict__ attract) {
  int b = threadIdx.x;
  if (b >= NB_) return;
  float best = sp01[b * NPAIR_];
  int bi = 0;
  for (int p = 1; p < NPAIR_; p++) {
    float v = sp01[b * NPAIR_ + p];
    if (v < best) { best = v; bi = p; }
  }
  for (int k = 0; k < 40; k++)
    attract[b * 40 + k] = attrAll[(b * NPAIR_ + bi) * 40 + k];
}

// ---------------- code rows ----------------
__global__ __launch_bounds__(128)
void code_k(const float* __restrict__ emb, const float* __restrict__ attract,
            const float* __restrict__ enc, const float* __restrict__ Re,
            const float* __restrict__ Im, float* __restrict__ rows) {
  int bt = blockIdx.x, tid = threadIdx.x;
  int b = bt / TT_, t = bt % TT_;
  __shared__ float at[40];
  if (tid < 40) at[tid] = attract[b * 40 + tid];
  __syncthreads();
  long r0 = ((long)(b * 2 + 0) * TT_ + t) * KPACKP_;
  long r1 = ((long)(b * 2 + 1) * TT_ + t) * KPACKP_;
  for (int f = tid; f < FC_; f += 128) {
    const float4* e4 = (const float4*)(emb + ((long)bt * FC_ + f) * EMBD_);
    float l0 = 0.f, l1 = 0.f;
    #pragma unroll
    for (int q = 0; q < 5; q++) {
      float4 v = e4[q];
      l0 = fmaf(v.x, at[q*4+0], l0); l0 = fmaf(v.y, at[q*4+1], l0);
      l0 = fmaf(v.z, at[q*4+2], l0); l0 = fmaf(v.w, at[q*4+3], l0);
      l1 = fmaf(v.x, at[20+q*4+0], l1); l1 = fmaf(v.y, at[20+q*4+1], l1);
      l1 = fmaf(v.z, at[20+q*4+2], l1); l1 = fmaf(v.w, at[20+q*4+3], l1);
    }
    if (f < AE_) {
      float fe = enc[bt * AE_ + f];
      rows[r0 + f] = l0 * fe;
      rows[r1 + f] = l1 * fe;
    } else {
      int j = f - AE_;
      float re = Re[bt * NFREQ_ + j], im = Im[bt * NFREQ_ + j];
      rows[r0 + 256 + j] = l0 * re;
      rows[r0 + 385 + j] = l0 * im;
      rows[r1 + 256 + j] = l1 * re;
      rows[r1 + 385 + j] = l1 * im;
    }
  }
  if (tid < KPACKP_ - KPACK_) {
    rows[r0 + KPACK_ + tid] = 0.f;
    rows[r1 + KPACK_ + tid] = 0.f;
  }
}

// ---------------- overlap-add ----------------
__global__ void ola_k(const float* __restrict__ tot, float* __restrict__ out) {
  int idx = blockIdx.x * blockDim.x + threadIdx.x;
  if (idx >= NB_ * 2 * LAUD_) return;
  int l = idx % LAUD_;
  int bc = idx / LAUD_;
  int tlo = (l >= NFFT_) ? ((l - NFFT_) >> 6) + 1 : 0;
  int thi = min(TT_ - 1, l >> 6);
  float acc = 0.f;
  for (int t = tlo; t <= thi; t++)
    acc += tot[((long)bc * TT_ + t) * NFFT_ + (l - (t << 6))];
  out[idx] = acc;
}

// ---------------- host orchestration ----------------
extern "C" void kernel_launch(void* const* d_in, const int* in_sizes, int n_in,
                              void* d_out, int out_size) {
  const float* audios = (const float*)d_in[0];
  const float* enc_w  = (const float*)d_in[1];
  const float* enc_b  = (const float*)d_in[2];
  const float* bgam   = (const float*)d_in[3];
  const float* bbet   = (const float*)d_in[4];
  const float* bw     = (const float*)d_in[5];
  const float* bbi    = (const float*)d_in[6];
  const float* c1w    = (const float*)d_in[7];
  const float* c1b    = (const float*)d_in[8];
  const float* p1     = (const float*)d_in[9];
  const float* g1g    = (const float*)d_in[10];
  const float* g1b    = (const float*)d_in[11];
  const float* dwv    = (const float*)d_in[12];
  const float* p2     = (const float*)d_in[13];
  const float* g2g    = (const float*)d_in[14];
  const float* g2b    = (const float*)d_in[15];
  const float* c2w    = (const float*)d_in[16];
  const float* c2b    = (const float*)d_in[17];
  const float* sw     = (const float*)d_in[18];
  const float* sb     = (const float*)d_in[19];
  const float* anchors= (const float*)d_in[20];
  const float* dec_w  = (const float*)d_in[21];
  const float* dec_b  = (const float*)d_in[22];
  float* out = (float*)d_out;

  float *frames,*enc,*Re,*Im,*mag,*xc,*x,*y1,*y2,*emb,*rows,*tot;
  float *apart,*attrAll,*sp01,*attv;
  float *c256,*s256,*win,*invwin,*Bpack,*biasPack,*Wg,*uv,*vv;
  double *dstat;
  cudaGetSymbolAddress((void**)&frames, g_frames);
  cudaGetSymbolAddress((void**)&enc,    g_enc);
  cudaGetSymbolAddress((void**)&Re,     g_Re);
  cudaGetSymbolAddress((void**)&Im,     g_Im);
  cudaGetSymbolAddress((void**)&mag,    g_mag);
  cudaGetSymbolAddress((void**)&xc,     g_xc);
  cudaGetSymbolAddress((void**)&x,      g_x);
  cudaGetSymbolAddress((void**)&y1,     g_y1);
  cudaGetSymbolAddress((void**)&y2,     g_y2);
  cudaGetSymbolAddress((void**)&emb,    g_emb);
  cudaGetSymbolAddress((void**)&rows,   g_rows);
  cudaGetSymbolAddress((void**)&tot,    g_tot);
  cudaGetSymbolAddress((void**)&dstat,  g_dstat);
  cudaGetSymbolAddress((void**)&apart,  g_apart);
  cudaGetSymbolAddress((void**)&attrAll,g_attrAll);
  cudaGetSymbolAddress((void**)&sp01,   g_sp01);
  cudaGetSymbolAddress((void**)&attv,   g_att);
  cudaGetSymbolAddress((void**)&c256,   g_c256);
  cudaGetSymbolAddress((void**)&s256,   g_s256);
  cudaGetSymbolAddress((void**)&win,    g_win);
  cudaGetSymbolAddress((void**)&invwin, g_invwin);
  cudaGetSymbolAddress((void**)&Bpack,  g_Bpack);
  cudaGetSymbolAddress((void**)&biasPack, g_biasPack);
  cudaGetSymbolAddress((void**)&Wg,     g_Wg);
  cudaGetSymbolAddress((void**)&uv,     g_u);
  cudaGetSymbolAddress((void**)&vv,     g_v);

  const int M = MROWS_;

  init_tables_k<<<1,256>>>(c256, s256, win, invwin, dstat);
  pack_k<<<KPACK_,256>>>(dec_w, dec_b, c256, s256, invwin, Bpack, biasPack);
  prep_c2_k<<<dim3(NBLK_,2),128>>>(c2w, g2g, g2b, Wg, uv, vv);
  frames_k<<<M,256>>>(audios, frames);

  // encoder: relu(frames @ enc_w + enc_b)
  gemmT<1,false><<<dim3(2,63),256>>>(frames, enc_w, enc_b, enc, M, 256, 256, 256,
                                     nullptr, nullptr, nullptr, nullptr, nullptr);
  fft_k<<<M,256>>>(frames, win, c256, s256, Re, Im, mag);
  cln_k<<<M,128>>>(enc, mag, bgam, bbet, xc);
  // bottleneck (K=385, lda=400 zero-padded)
  gemmT<0,false><<<dim3(2,63),256>>>(xc, bw, bbi, x, M, 256, 385, FCP_,
                                     nullptr, nullptr, nullptr, nullptr, nullptr);

  for (int i = 0; i < NBLK_; i++) {
    int di = 1 << (i & 7);
    double* dA = dstat + (2*i) * 16;
    double* dB = dstat + (2*i + 1) * 16;
    // c1 GEMM + prelu + fused y1-stat accumulation
    gemmT<2,true><<<dim3(4,63),256>>>(x, c1w + (long)i*BTL_*HH_, c1b + i*HH_, y1,
                                      M, 512, 256, 256, p1 + i*HH_,
                                      nullptr, nullptr, nullptr, dA);
    // gLN1 finalize + dwconv + prelu2 + fused y2-stat accumulation
    dwconv2_k<<<MROWS_*HH_/4/256,256>>>(y1, y2, dwv + i*3*HH_, dA, dB,
                                        g1g + i*HH_, g1b + i*HH_, p2 + i*HH_, di);
    // c2 GEMM with gLN2 finalize in epilogue + residual add
    gemmT<3,false><<<dim3(2,63),256>>>(y2, Wg + (long)i*HH_*BTL_, c2b + i*BTL_, x,
                                       M, 256, 512, 512, nullptr,
                                       uv + i*BTL_, vv + i*BTL_, dB, nullptr);
  }

  // separator: x @ sep_w + sep_b (N=7700)
  gemmT<0,false><<<dim3(61,63),256>>>(x, sw, sb, emb, M, NSEP_, 256, 256,
                                      nullptr, nullptr, nullptr, nullptr, nullptr);
  attr_part_k<<<NB_*NPAIR_*ANS_,128>>>(emb, anchors, apart);
  attr_comb_k<<<NB_*NPAIR_,64>>>(apart, attrAll, sp01);
  choose_k<<<1,32>>>(sp01, attrAll, attv);
  code_k<<<M,128>>>(emb, attv, enc, Re, Im, rows);
  // fused conv-decode + iSTFT GEMM (K=514, lda=528 zero-padded)
  gemmT<0,false><<<dim3(2,125),256>>>(rows, Bpack, biasPack, tot, MROWS2_, 256, 514, KPACKP_,
                                      nullptr, nullptr, nullptr, nullptr, nullptr);
  ola_k<<<(NB_*2*LAUD_+255)/256,256>>>(tot, out);
}